// round 4
// baseline (speedup 1.0000x reference)
#include <cuda_runtime.h>
#include <cstdint>

// ---------------------------------------------------------------------------
// Problem constants (fixed by the dataset)
// ---------------------------------------------------------------------------
#define NNODES 50000
#define MAXF   1536
#define MAXE   400000

// Scratch (allocation-free: __device__ globals). Two ping-pong feature buffers
// sized for the widest layer (N x 1536 fp32 = 307 MB each).
__device__ float g_B0[(size_t)NNODES * MAXF];
__device__ float g_B1[(size_t)NNODES * MAXF];
__device__ float g_deg[NNODES];
__device__ float g_dinv[NNODES];
__device__ float g_norm[MAXE];

// ---------------------------------------------------------------------------
// Utility kernels
// ---------------------------------------------------------------------------
__global__ void zero_kernel(float* __restrict__ p, size_t n) {
    size_t i4 = ((size_t)blockIdx.x * blockDim.x + threadIdx.x) * 4;
    if (i4 + 3 < n) {
        *(float4*)(p + i4) = make_float4(0.f, 0.f, 0.f, 0.f);
    } else if (i4 < n) {
        for (size_t k = i4; k < n; k++) p[k] = 0.f;
    }
}

__global__ void deg_kernel(const int* __restrict__ dst, float* __restrict__ deg, int E) {
    int e = blockIdx.x * blockDim.x + threadIdx.x;
    if (e < E) atomicAdd(&deg[dst[e]], 1.0f);
}

__global__ void dinv_kernel(const float* __restrict__ deg, float* __restrict__ dinv, int n) {
    int i = blockIdx.x * blockDim.x + threadIdx.x;
    if (i < n) dinv[i] = rsqrtf(deg[i] + 1.0f);
}

__global__ void norm_kernel(const int* __restrict__ src, const int* __restrict__ dst,
                            const float* __restrict__ dinv, float* __restrict__ norm, int E) {
    int e = blockIdx.x * blockDim.x + threadIdx.x;
    if (e < E) norm[e] = dinv[src[e]] * dinv[dst[e]];
}

// ---------------------------------------------------------------------------
// SGEMM: C[M,N] = A[M,K] * B[K,N], all row-major fp32.
// 128x128 block tile, BK=8, 256 threads, 8x8 per-thread micro tile.
// K is always a multiple of 8 here (768/1536/384/192).
// ---------------------------------------------------------------------------
#define BM 128
#define BN 128
#define BK 8
#define TM 8
#define TN 8

__global__ __launch_bounds__(256) void sgemm_kernel(
    const float* __restrict__ A, const float* __restrict__ B,
    float* __restrict__ C, int M, int K, int N)
{
    __shared__ __align__(16) float As[BK][BM];
    __shared__ __align__(16) float Bs[BK][BN];

    const int tid = threadIdx.x;
    const int block_row = blockIdx.y * BM;
    const int block_col = blockIdx.x * BN;

    const int tx = tid & 15;          // 0..15
    const int ty = tid >> 4;          // 0..15
    const int row0 = ty * TM;         // 0..120
    const int col0 = tx * TN;         // 0..120

    // A tile: 128 rows x 8 k -> 256 float4, one per thread
    const int a_row = tid >> 1;
    const int a_k   = (tid & 1) * 4;
    // B tile: 8 k x 128 cols -> 256 float4, one per thread
    const int b_k   = tid >> 5;
    const int b_col = (tid & 31) * 4;

    float acc[TM][TN];
    #pragma unroll
    for (int i = 0; i < TM; i++)
        #pragma unroll
        for (int j = 0; j < TN; j++) acc[i][j] = 0.f;

    for (int k0 = 0; k0 < K; k0 += BK) {
        // ---- load A tile (K is a multiple of 4 -> float4 always aligned) ----
        float4 av = make_float4(0.f, 0.f, 0.f, 0.f);
        {
            int gr = block_row + a_row;
            if (gr < M) av = *(const float4*)(A + (size_t)gr * K + (k0 + a_k));
        }
        As[a_k + 0][a_row] = av.x;
        As[a_k + 1][a_row] = av.y;
        As[a_k + 2][a_row] = av.z;
        As[a_k + 3][a_row] = av.w;

        // ---- load B tile ----
        // Vector path ONLY when N % 4 == 0 (row stride stays 16B-aligned).
        // Otherwise (e.g. N=5 final layer) scalar loads: row base B + k*N is
        // not 16B aligned for odd k and LDG.128 would trap.
        float4 bv = make_float4(0.f, 0.f, 0.f, 0.f);
        {
            int gc = block_col + b_col;
            const float* bp = B + (size_t)(k0 + b_k) * N;
            if ((N & 3) == 0) {
                if (gc + 3 < N) bv = *(const float4*)(bp + gc);
            } else {
                if (gc + 0 < N) bv.x = bp[gc + 0];
                if (gc + 1 < N) bv.y = bp[gc + 1];
                if (gc + 2 < N) bv.z = bp[gc + 2];
                if (gc + 3 < N) bv.w = bp[gc + 3];
            }
        }
        *(float4*)&Bs[b_k][b_col] = bv;

        __syncthreads();

        #pragma unroll
        for (int kk = 0; kk < BK; kk++) {
            float areg[TM], breg[TN];
            #pragma unroll
            for (int i = 0; i < TM; i++) areg[i] = As[kk][row0 + i];
            #pragma unroll
            for (int j = 0; j < TN; j++) breg[j] = Bs[kk][col0 + j];
            #pragma unroll
            for (int i = 0; i < TM; i++)
                #pragma unroll
                for (int j = 0; j < TN; j++)
                    acc[i][j] += areg[i] * breg[j];
        }
        __syncthreads();
    }

    // ---- store (scalar; C row stride not guaranteed 16B-aligned for N=5) ----
    #pragma unroll
    for (int i = 0; i < TM; i++) {
        int r = block_row + row0 + i;
        if (r >= M) continue;
        float* crow = C + (size_t)r * N;
        #pragma unroll
        for (int j = 0; j < TN; j++) {
            int c = block_col + col0 + j;
            if (c < N) crow[c] = acc[i][j];
        }
    }
}

// ---------------------------------------------------------------------------
// Edge scatter: agg[dst] += h[src] * norm   (F multiple of 4; warp per edge,
// float4 loads + red.global.add.v4.f32 no-return atomics)
// ---------------------------------------------------------------------------
__global__ void scatter_kernel(const float* __restrict__ h, float* __restrict__ agg,
                               const int* __restrict__ src, const int* __restrict__ dst,
                               const float* __restrict__ norm, int E, int F)
{
    int warp = (int)((blockIdx.x * blockDim.x + threadIdx.x) >> 5);
    int lane = threadIdx.x & 31;
    if (warp >= E) return;
    int s = src[warp];
    int d = dst[warp];
    float w = norm[warp];
    const float* hp = h + (size_t)s * F;
    float* ap = agg + (size_t)d * F;
    for (int f = lane * 4; f < F; f += 128) {
        float4 v = *(const float4*)(hp + f);
        v.x *= w; v.y *= w; v.z *= w; v.w *= w;
        asm volatile("red.global.add.v4.f32 [%0], {%1,%2,%3,%4};"
                     :: "l"(ap + f), "f"(v.x), "f"(v.y), "f"(v.z), "f"(v.w)
                     : "memory");
    }
}

// scalar variant for F not multiple of 4 (final layer, F=5)
__global__ void scatter_small_kernel(const float* __restrict__ h, float* __restrict__ agg,
                                     const int* __restrict__ src, const int* __restrict__ dst,
                                     const float* __restrict__ norm, int E, int F)
{
    int e = blockIdx.x * blockDim.x + threadIdx.x;
    if (e >= E) return;
    int s = src[e];
    int d = dst[e];
    float w = norm[e];
    const float* hp = h + (size_t)s * F;
    float* ap = agg + (size_t)d * F;
    for (int f = 0; f < F; f++)
        atomicAdd(ap + f, hp[f] * w);
}

// ---------------------------------------------------------------------------
// Finalize: out = (agg + h*dinv^2 + bias), optional relu
// ---------------------------------------------------------------------------
__global__ void finalize_kernel(const float* __restrict__ hg, const float* __restrict__ agg,
                                const float* __restrict__ bias, const float* __restrict__ dinv,
                                float* __restrict__ out, int Nn, int F, int do_relu)
{
    int idx = blockIdx.x * blockDim.x + threadIdx.x;
    int total = Nn * F;
    if (idx >= total) return;
    int i = idx / F;
    int f = idx - i * F;
    float di = dinv[i];
    float v = agg[idx] + hg[idx] * (di * di) + bias[f];
    if (do_relu) v = fmaxf(v, 0.f);
    out[idx] = v;
}

// ---------------------------------------------------------------------------
// kernel_launch
// ---------------------------------------------------------------------------
extern "C" void kernel_launch(void* const* d_in, const int* in_sizes, int n_in,
                              void* d_out, int out_size)
{
    const float* x   = (const float*)d_in[0];
    const int*   ei  = (const int*)d_in[1];
    const int    E   = in_sizes[1] / 2;
    const int*   src = ei;
    const int*   dst = ei + E;

    const float* W[5];
    const float* b[5];
    for (int i = 0; i < 5; i++) {
        W[i] = (const float*)d_in[2 + 2 * i];
        b[i] = (const float*)d_in[3 + 2 * i];
    }

    float *B0, *B1, *deg, *dinv, *norm;
    cudaGetSymbolAddress((void**)&B0,   g_B0);
    cudaGetSymbolAddress((void**)&B1,   g_B1);
    cudaGetSymbolAddress((void**)&deg,  g_deg);
    cudaGetSymbolAddress((void**)&dinv, g_dinv);
    cudaGetSymbolAddress((void**)&norm, g_norm);

    // ---- degree / norm prep ----
    zero_kernel<<<(NNODES / 4 + 255) / 256, 256>>>(deg, (size_t)NNODES);
    deg_kernel<<<(E + 255) / 256, 256>>>(dst, deg, E);
    dinv_kernel<<<(NNODES + 255) / 256, 256>>>(deg, dinv, NNODES);
    norm_kernel<<<(E + 255) / 256, 256>>>(src, dst, dinv, norm, E);

    const int Ks[5] = {768, 1536, 768, 384, 192};
    const int Fo[5] = {1536, 768, 384, 192, 5};

    float* out_h = (float*)d_out;                          // [N,192]
    float* out_o = (float*)d_out + (size_t)NNODES * 192;   // [N,5]

    const float* in = x;
    for (int l = 0; l < 5; l++) {
        const int K = Ks[l];
        const int F = Fo[l];
        const size_t nAgg = (size_t)NNODES * F;

        // 1) GEMM: B0 = in @ W[l]
        dim3 grid((F + BN - 1) / BN, (NNODES + BM - 1) / BM);
        sgemm_kernel<<<grid, 256>>>(in, W[l], B0, NNODES, K, F);

        // 2) zero agg buffer (B1's first N*F elements; its old contents were
        //    consumed by the GEMM above)
        zero_kernel<<<(unsigned)((nAgg / 4 + 255) / 256), 256>>>(B1, nAgg);

        // 3) edge scatter: B1[dst] += B0[src] * norm
        if ((F & 3) == 0) {
            long long threads = (long long)E * 32;
            scatter_kernel<<<(unsigned)((threads + 255) / 256), 256>>>(B0, B1, src, dst, norm, E, F);
        } else {
            scatter_small_kernel<<<(E + 255) / 256, 256>>>(B0, B1, src, dst, norm, E, F);
        }

        // 4) finalize: self-loop + bias (+ relu for layers 1-4)
        float* dest = (l == 4) ? out_o : B1;
        finalize_kernel<<<(unsigned)((nAgg + 255) / 256), 256>>>(
            B0, B1, b[l], dinv, dest, NNODES, F, (l < 4) ? 1 : 0);

        // after layer 4, B1 holds h -> copy to output before layer 5 clobbers it
        if (l == 3) {
            cudaMemcpyAsync(out_h, B1, (size_t)NNODES * 192 * sizeof(float),
                            cudaMemcpyDeviceToDevice);
        }

        in = B1;
    }
}

// round 6
// speedup vs baseline: 1.8721x; 1.8721x over previous
#include <cuda_runtime.h>
#include <cuda_bf16.h>
#include <cstdint>

// ---------------------------------------------------------------------------
// Problem constants (fixed by the dataset)
// ---------------------------------------------------------------------------
#define NNODES 50000
#define MAXF   1536
#define MAXE   400000

// Scratch (allocation-free: __device__ globals)
__device__ float g_B0[(size_t)NNODES * MAXF];
__device__ float g_B1[(size_t)NNODES * MAXF];
__device__ __nv_bfloat16 g_Ahi[(size_t)NNODES * MAXF];
__device__ __nv_bfloat16 g_Alo[(size_t)NNODES * MAXF];
__device__ __nv_bfloat16 g_Whi[(size_t)MAXF * MAXF];
__device__ __nv_bfloat16 g_Wlo[(size_t)MAXF * MAXF];
__device__ float g_deg[NNODES];
__device__ float g_dinv[NNODES];
__device__ float g_norm[MAXE];

__device__ __forceinline__ uint32_t smem_u32(const void* p) {
    uint32_t a;
    asm("{ .reg .u64 t; cvta.to.shared.u64 t, %1; cvt.u32.u64 %0, t; }" : "=r"(a) : "l"(p));
    return a;
}

// ---------------------------------------------------------------------------
// Utility kernels
// ---------------------------------------------------------------------------
__global__ void zero_kernel(float* __restrict__ p, size_t n) {
    size_t i4 = ((size_t)blockIdx.x * blockDim.x + threadIdx.x) * 4;
    if (i4 + 3 < n) {
        *(float4*)(p + i4) = make_float4(0.f, 0.f, 0.f, 0.f);
    } else if (i4 < n) {
        for (size_t k = i4; k < n; k++) p[k] = 0.f;
    }
}

__global__ void deg_kernel(const int* __restrict__ dst, float* __restrict__ deg, int E) {
    int e = blockIdx.x * blockDim.x + threadIdx.x;
    if (e < E) atomicAdd(&deg[dst[e]], 1.0f);
}

__global__ void dinv_kernel(const float* __restrict__ deg, float* __restrict__ dinv, int n) {
    int i = blockIdx.x * blockDim.x + threadIdx.x;
    if (i < n) dinv[i] = rsqrtf(deg[i] + 1.0f);
}

__global__ void norm_kernel(const int* __restrict__ src, const int* __restrict__ dst,
                            const float* __restrict__ dinv, float* __restrict__ norm, int E) {
    int e = blockIdx.x * blockDim.x + threadIdx.x;
    if (e < E) norm[e] = dinv[src[e]] * dinv[dst[e]];
}

// fp32 -> bf16 hi/lo split (vectorized x4; n multiple of 4)
__global__ void aconv_kernel(const float* __restrict__ in, __nv_bfloat16* __restrict__ hi,
                             __nv_bfloat16* __restrict__ lo, size_t n4) {
    size_t i = (size_t)blockIdx.x * blockDim.x + threadIdx.x;
    if (i >= n4) return;
    float4 a = ((const float4*)in)[i];
    __nv_bfloat16 h0 = __float2bfloat16(a.x), h1 = __float2bfloat16(a.y);
    __nv_bfloat16 h2 = __float2bfloat16(a.z), h3 = __float2bfloat16(a.w);
    __nv_bfloat16 l0 = __float2bfloat16(a.x - __bfloat162float(h0));
    __nv_bfloat16 l1 = __float2bfloat16(a.y - __bfloat162float(h1));
    __nv_bfloat16 l2 = __float2bfloat16(a.z - __bfloat162float(h2));
    __nv_bfloat16 l3 = __float2bfloat16(a.w - __bfloat162float(h3));
    __nv_bfloat162* H = (__nv_bfloat162*)hi;
    __nv_bfloat162* L = (__nv_bfloat162*)lo;
    H[2 * i]     = __halves2bfloat162(h0, h1);
    H[2 * i + 1] = __halves2bfloat162(h2, h3);
    L[2 * i]     = __halves2bfloat162(l0, l1);
    L[2 * i + 1] = __halves2bfloat162(l2, l3);
}

// W [K,N] fp32 -> Wt_hi/Wt_lo [N,K] bf16 (transpose + split)
__global__ void wconv_kernel(const float* __restrict__ W, __nv_bfloat16* __restrict__ Thi,
                             __nv_bfloat16* __restrict__ Tlo, int K, int N) {
    int idx = blockIdx.x * blockDim.x + threadIdx.x;
    if (idx >= K * N) return;
    int k = idx / N, n = idx - k * N;
    float w = W[idx];
    __nv_bfloat16 h = __float2bfloat16(w);
    Thi[(size_t)n * K + k] = h;
    Tlo[(size_t)n * K + k] = __float2bfloat16(w - __bfloat162float(h));
}

// io = relu(io + bias)  (vectorized x4; F multiple of 4)
__global__ void biasact_kernel(float* __restrict__ io, const float* __restrict__ bias,
                               size_t n4, int F) {
    size_t i = (size_t)blockIdx.x * blockDim.x + threadIdx.x;
    if (i >= n4) return;
    size_t i4 = i * 4;
    int f = (int)(i4 % F);
    float4 v = *(float4*)(io + i4);
    v.x = fmaxf(v.x + bias[f + 0], 0.f);
    v.y = fmaxf(v.y + bias[f + 1], 0.f);
    v.z = fmaxf(v.z + bias[f + 2], 0.f);
    v.w = fmaxf(v.w + bias[f + 3], 0.f);
    *(float4*)(io + i4) = v;
}

// ---------------------------------------------------------------------------
// mma.sync bf16x3 GEMM: C[M,N] = Ahi*Whi + Alo*Whi + Ahi*Wlo
//   A*: [M,K] bf16 row-major.  W*: [N,K] bf16 row-major (= W^T, K-major).
//   128x128x32 block tile, 256 thr = 8 warps (2m x 4n), 64x32 warp tile,
//   cp.async double buffering, XOR-swizzled smem, ldmatrix fragments.
// ---------------------------------------------------------------------------
#define TBK 32   // k per chunk (32 bf16 = 64B/row = 4x16B chunks)

__global__ __launch_bounds__(256, 2)
void gemm_mma_kernel(const __nv_bfloat16* __restrict__ Ahi, const __nv_bfloat16* __restrict__ Alo,
                     const __nv_bfloat16* __restrict__ Whi, const __nv_bfloat16* __restrict__ Wlo,
                     float* __restrict__ C, int M, int K, int N)
{
    __shared__ __align__(1024) __nv_bfloat16 As[2][128 * TBK];
    __shared__ __align__(1024) __nv_bfloat16 Bs[2][128 * TBK];

    const int tid  = threadIdx.x;
    const int lane = tid & 31;
    const int wid  = tid >> 5;
    const int wm   = (wid & 1) * 64;    // warp m offset in tile
    const int wn   = (wid >> 1) * 32;   // warp n offset in tile
    const int m0   = blockIdx.y * 128;
    const int n0   = blockIdx.x * 128;

    const int kc = K / TBK;     // chunks per pass
    const int KB = kc * 3;      // 3 passes: hi*hi, lo*hi, hi*lo

    const uint32_t sA0 = smem_u32(&As[0][0]);
    const uint32_t sB0 = smem_u32(&Bs[0][0]);

    float acc[4][4][4];
    #pragma unroll
    for (int mi = 0; mi < 4; mi++)
        #pragma unroll
        for (int ni = 0; ni < 4; ni++)
            #pragma unroll
            for (int q = 0; q < 4; q++) acc[mi][ni][q] = 0.f;

    // per-thread cp.async assignment: 2 16B-chunks each for A and B
    // global chunk idx in [0,512): row = idx>>2, ch = idx&3
    auto issue = [&](int kb, int buf) {
        const int pass = kb / kc;
        const int kk = (kb - pass * kc) * TBK;
        const __nv_bfloat16* Ap = (pass == 1) ? Alo : Ahi;
        const __nv_bfloat16* Bp = (pass == 2) ? Wlo : Whi;
        #pragma unroll
        for (int h = 0; h < 2; h++) {
            const int idx = tid + h * 256;
            const int r = idx >> 2, ch = idx & 3;
            const uint32_t soff = (uint32_t)r * 64 + (uint32_t)((ch ^ (r & 3)) * 16);
            // A
            {
                const int gr = m0 + r;
                const int ok = (gr < M) ? 16 : 0;
                const int grc = ok ? gr : 0;
                const void* ga = Ap + (size_t)grc * K + kk + ch * 8;
                uint32_t da = sA0 + (uint32_t)buf * 8192 + soff;
                asm volatile("cp.async.cg.shared.global [%0], [%1], 16, %2;"
                             :: "r"(da), "l"(ga), "r"(ok));
            }
            // B
            {
                const int gr = n0 + r;
                const int ok = (gr < N) ? 16 : 0;
                const int grc = ok ? gr : 0;
                const void* gb = Bp + (size_t)grc * K + kk + ch * 8;
                uint32_t db = sB0 + (uint32_t)buf * 8192 + soff;
                asm volatile("cp.async.cg.shared.global [%0], [%1], 16, %2;"
                             :: "r"(db), "l"(gb), "r"(ok));
            }
        }
        asm volatile("cp.async.commit_group;" ::: "memory");
    };

    auto compute = [&](int buf) {
        const uint32_t sA = sA0 + (uint32_t)buf * 8192;
        const uint32_t sB = sB0 + (uint32_t)buf * 8192;
        #pragma unroll
        for (int ks = 0; ks < 2; ks++) {   // two k16 steps in TBK=32
            uint32_t a[4][4];
            uint32_t b[4][2];
            // A fragments: ldmatrix.x4 per m16 tile
            #pragma unroll
            for (int mi = 0; mi < 4; mi++) {
                const int r = wm + mi * 16 + (lane & 15);
                const int ch = ks * 2 + (lane >> 4);
                const uint32_t addr = sA + (uint32_t)r * 64 + (uint32_t)((ch ^ (r & 3)) * 16);
                asm volatile("ldmatrix.sync.aligned.m8n8.x4.shared.b16 {%0,%1,%2,%3}, [%4];"
                             : "=r"(a[mi][0]), "=r"(a[mi][1]), "=r"(a[mi][2]), "=r"(a[mi][3])
                             : "r"(addr));
            }
            // B fragments: each ldmatrix.x4 covers two n8 groups
            #pragma unroll
            for (int g = 0; g < 2; g++) {
                const int r = wn + g * 16 + (lane & 7) + ((lane >> 4) << 3);
                const int ch = ks * 2 + ((lane >> 3) & 1);
                const uint32_t addr = sB + (uint32_t)r * 64 + (uint32_t)((ch ^ (r & 3)) * 16);
                asm volatile("ldmatrix.sync.aligned.m8n8.x4.shared.b16 {%0,%1,%2,%3}, [%4];"
                             : "=r"(b[g * 2][0]), "=r"(b[g * 2][1]),
                               "=r"(b[g * 2 + 1][0]), "=r"(b[g * 2 + 1][1])
                             : "r"(addr));
            }
            #pragma unroll
            for (int mi = 0; mi < 4; mi++)
                #pragma unroll
                for (int ni = 0; ni < 4; ni++) {
                    asm volatile(
                        "mma.sync.aligned.m16n8k16.row.col.f32.bf16.bf16.f32 "
                        "{%0,%1,%2,%3}, {%4,%5,%6,%7}, {%8,%9}, {%0,%1,%2,%3};"
                        : "+f"(acc[mi][ni][0]), "+f"(acc[mi][ni][1]),
                          "+f"(acc[mi][ni][2]), "+f"(acc[mi][ni][3])
                        : "r"(a[mi][0]), "r"(a[mi][1]), "r"(a[mi][2]), "r"(a[mi][3]),
                          "r"(b[ni][0]), "r"(b[ni][1]));
                }
        }
    };

    issue(0, 0);
    for (int kb = 0; kb < KB; kb++) {
        const int buf = kb & 1;
        if (kb + 1 < KB) {
            issue(kb + 1, buf ^ 1);
            asm volatile("cp.async.wait_group 1;" ::: "memory");
        } else {
            asm volatile("cp.async.wait_group 0;" ::: "memory");
        }
        __syncthreads();
        compute(buf);
        __syncthreads();
    }

    // epilogue: C fragment -> gmem (float2, 8B aligned: N % 8 == 0, col even)
    #pragma unroll
    for (int mi = 0; mi < 4; mi++) {
        const int r0 = m0 + wm + mi * 16 + (lane >> 2);
        #pragma unroll
        for (int ni = 0; ni < 4; ni++) {
            const int col = n0 + wn + ni * 8 + 2 * (lane & 3);
            if (col >= N) continue;
            if (r0 < M) {
                float2 v = make_float2(acc[mi][ni][0], acc[mi][ni][1]);
                *(float2*)(C + (size_t)r0 * N + col) = v;
            }
            if (r0 + 8 < M) {
                float2 v = make_float2(acc[mi][ni][2], acc[mi][ni][3]);
                *(float2*)(C + (size_t)(r0 + 8) * N + col) = v;
            }
        }
    }
}

// ---------------------------------------------------------------------------
// fp32 SGEMM (tiny final layer, N=5)
// ---------------------------------------------------------------------------
#define BM 128
#define BN 128
#define BK 8
#define TM 8
#define TN 8

__global__ __launch_bounds__(256) void sgemm_kernel(
    const float* __restrict__ A, const float* __restrict__ B,
    float* __restrict__ C, int M, int K, int N)
{
    __shared__ __align__(16) float As[BK][BM];
    __shared__ __align__(16) float Bs[BK][BN];

    const int tid = threadIdx.x;
    const int block_row = blockIdx.y * BM;
    const int block_col = blockIdx.x * BN;
    const int tx = tid & 15, ty = tid >> 4;
    const int row0 = ty * TM, col0 = tx * TN;
    const int a_row = tid >> 1, a_k = (tid & 1) * 4;
    const int b_k = tid >> 5, b_col = (tid & 31) * 4;

    float acc[TM][TN];
    #pragma unroll
    for (int i = 0; i < TM; i++)
        #pragma unroll
        for (int j = 0; j < TN; j++) acc[i][j] = 0.f;

    for (int k0 = 0; k0 < K; k0 += BK) {
        float4 av = make_float4(0.f, 0.f, 0.f, 0.f);
        {
            int gr = block_row + a_row;
            if (gr < M) av = *(const float4*)(A + (size_t)gr * K + (k0 + a_k));
        }
        As[a_k + 0][a_row] = av.x;
        As[a_k + 1][a_row] = av.y;
        As[a_k + 2][a_row] = av.z;
        As[a_k + 3][a_row] = av.w;

        float4 bv = make_float4(0.f, 0.f, 0.f, 0.f);
        {
            int gc = block_col + b_col;
            const float* bp = B + (size_t)(k0 + b_k) * N;
            if ((N & 3) == 0) {
                if (gc + 3 < N) bv = *(const float4*)(bp + gc);
            } else {
                if (gc + 0 < N) bv.x = bp[gc + 0];
                if (gc + 1 < N) bv.y = bp[gc + 1];
                if (gc + 2 < N) bv.z = bp[gc + 2];
                if (gc + 3 < N) bv.w = bp[gc + 3];
            }
        }
        *(float4*)&Bs[b_k][b_col] = bv;

        __syncthreads();
        #pragma unroll
        for (int kk = 0; kk < BK; kk++) {
            float areg[TM], breg[TN];
            #pragma unroll
            for (int i = 0; i < TM; i++) areg[i] = As[kk][row0 + i];
            #pragma unroll
            for (int j = 0; j < TN; j++) breg[j] = Bs[kk][col0 + j];
            #pragma unroll
            for (int i = 0; i < TM; i++)
                #pragma unroll
                for (int j = 0; j < TN; j++)
                    acc[i][j] += areg[i] * breg[j];
        }
        __syncthreads();
    }

    #pragma unroll
    for (int i = 0; i < TM; i++) {
        int r = block_row + row0 + i;
        if (r >= M) continue;
        float* crow = C + (size_t)r * N;
        #pragma unroll
        for (int j = 0; j < TN; j++) {
            int c = block_col + col0 + j;
            if (c < N) crow[c] = acc[i][j];
        }
    }
}

// ---------------------------------------------------------------------------
// Edge scatter: agg[dst] += h[src] * norm   (F multiple of 4; warp per edge)
// ---------------------------------------------------------------------------
__global__ void scatter_kernel(const float* __restrict__ h, float* __restrict__ agg,
                               const int* __restrict__ src, const int* __restrict__ dst,
                               const float* __restrict__ norm, int E, int F)
{
    int warp = (int)((blockIdx.x * blockDim.x + threadIdx.x) >> 5);
    int lane = threadIdx.x & 31;
    if (warp >= E) return;
    int s = src[warp];
    int d = dst[warp];
    float w = norm[warp];
    const float* hp = h + (size_t)s * F;
    float* ap = agg + (size_t)d * F;
    for (int f = lane * 4; f < F; f += 128) {
        float4 v = *(const float4*)(hp + f);
        v.x *= w; v.y *= w; v.z *= w; v.w *= w;
        asm volatile("red.global.add.v4.f32 [%0], {%1,%2,%3,%4};"
                     :: "l"(ap + f), "f"(v.x), "f"(v.y), "f"(v.z), "f"(v.w)
                     : "memory");
    }
}

__global__ void scatter_small_kernel(const float* __restrict__ h, float* __restrict__ agg,
                                     const int* __restrict__ src, const int* __restrict__ dst,
                                     const float* __restrict__ norm, int E, int F)
{
    int e = blockIdx.x * blockDim.x + threadIdx.x;
    if (e >= E) return;
    int s = src[e];
    int d = dst[e];
    float w = norm[e];
    const float* hp = h + (size_t)s * F;
    float* ap = agg + (size_t)d * F;
    for (int f = 0; f < F; f++)
        atomicAdd(ap + f, hp[f] * w);
}

// ---------------------------------------------------------------------------
// Finalize: out = agg + hg*dinv^2 (+ bias) (+ relu). bias may be null.
// ---------------------------------------------------------------------------
__global__ void finalize_kernel(const float* __restrict__ hg, const float* __restrict__ agg,
                                const float* __restrict__ bias, const float* __restrict__ dinv,
                                float* __restrict__ out, int Nn, int F, int do_relu)
{
    int idx = blockIdx.x * blockDim.x + threadIdx.x;
    int total = Nn * F;
    if (idx >= total) return;
    int i = idx / F;
    int f = idx - i * F;
    float di = dinv[i];
    float bb = bias ? bias[f] : 0.f;
    float v = agg[idx] + hg[idx] * (di * di) + bb;
    if (do_relu) v = fmaxf(v, 0.f);
    out[idx] = v;
}

// ---------------------------------------------------------------------------
// kernel_launch
// ---------------------------------------------------------------------------
extern "C" void kernel_launch(void* const* d_in, const int* in_sizes, int n_in,
                              void* d_out, int out_size)
{
    const float* x   = (const float*)d_in[0];
    const int*   ei  = (const int*)d_in[1];
    const int    E   = in_sizes[1] / 2;
    const int*   src = ei;
    const int*   dst = ei + E;

    const float* W[5];
    const float* b[5];
    for (int i = 0; i < 5; i++) {
        W[i] = (const float*)d_in[2 + 2 * i];
        b[i] = (const float*)d_in[3 + 2 * i];
    }

    float *B0, *B1, *deg, *dinv, *norm;
    __nv_bfloat16 *Ahi, *Alo, *Whi, *Wlo;
    cudaGetSymbolAddress((void**)&B0,   g_B0);
    cudaGetSymbolAddress((void**)&B1,   g_B1);
    cudaGetSymbolAddress((void**)&deg,  g_deg);
    cudaGetSymbolAddress((void**)&dinv, g_dinv);
    cudaGetSymbolAddress((void**)&norm, g_norm);
    cudaGetSymbolAddress((void**)&Ahi,  g_Ahi);
    cudaGetSymbolAddress((void**)&Alo,  g_Alo);
    cudaGetSymbolAddress((void**)&Whi,  g_Whi);
    cudaGetSymbolAddress((void**)&Wlo,  g_Wlo);

    const int MT = (NNODES + 127) / 128;   // 391 M-tiles

    // ---- degree / norm prep ----
    zero_kernel<<<(NNODES / 4 + 255) / 256, 256>>>(deg, (size_t)NNODES);
    deg_kernel<<<(E + 255) / 256, 256>>>(dst, deg, E);
    dinv_kernel<<<(NNODES + 255) / 256, 256>>>(deg, dinv, NNODES);
    norm_kernel<<<(E + 255) / 256, 256>>>(src, dst, dinv, norm, E);

    float* out_h = (float*)d_out;                          // [N,192]
    float* out_o = (float*)d_out + (size_t)NNODES * 192;   // [N,5]

    auto run_agg = [&](const float* gin, float* aggbuf, const float* bias, float* dest,
                       int F, int do_relu) {
        size_t nAgg = (size_t)NNODES * F;
        zero_kernel<<<(unsigned)((nAgg / 4 + 255) / 256), 256>>>(aggbuf, nAgg);
        if ((F & 3) == 0) {
            long long th = (long long)E * 32;
            scatter_kernel<<<(unsigned)((th + 255) / 256), 256>>>(gin, aggbuf, src, dst, norm, E, F);
        } else {
            scatter_small_kernel<<<(E + 255) / 256, 256>>>(gin, aggbuf, src, dst, norm, E, F);
        }
        finalize_kernel<<<(unsigned)((nAgg + 255) / 256), 256>>>(
            gin, aggbuf, bias, dinv, dest, NNODES, F, do_relu);
    };
    auto run_conv = [&](const float* in, int K) {
        size_t n4 = (size_t)NNODES * K / 4;
        aconv_kernel<<<(unsigned)((n4 + 255) / 256), 256>>>(in, Ahi, Alo, n4);
    };
    auto run_wconv = [&](const float* Wp, int K, int N) {
        wconv_kernel<<<(K * N + 255) / 256, 256>>>(Wp, Whi, Wlo, K, N);
    };
    auto run_gemm = [&](float* C, int K, int N) {
        dim3 grid((N + 127) / 128, MT);
        gemm_mma_kernel<<<grid, 256>>>(Ahi, Alo, Whi, Wlo, C, NNODES, K, N);
    };

    // ---- Layer 1: aggregate FIRST on width 768 (A(xW) == (Ax)W), then GEMM ----
    run_agg(x, B1, nullptr, B1, 768, 0);       // B1 = Ahat x
    run_conv(B1, 768);
    run_wconv(W[0], 768, 1536);
    run_gemm(B0, 768, 1536);                   // B0 = (Ahat x) W1
    {
        size_t n4 = (size_t)NNODES * 1536 / 4;
        biasact_kernel<<<(unsigned)((n4 + 255) / 256), 256>>>(B0, b[0], n4, 1536);
    }                                          // B0 = h1

    // ---- Layer 2: GEMM first (1536 -> 768), aggregate on 768 ----
    run_conv(B0, 1536);
    run_wconv(W[1], 1536, 768);
    run_gemm(B1, 1536, 768);                   // B1 = h1 W2
    run_agg(B1, B0, b[1], B0, 768, 1);         // B0 = h2

    // ---- Layer 3 ----
    run_conv(B0, 768);
    run_wconv(W[2], 768, 384);
    run_gemm(B1, 768, 384);
    run_agg(B1, B0, b[2], B0, 384, 1);         // B0 = h3

    // ---- Layer 4 (writes h4 straight into out_h) ----
    run_conv(B0, 384);
    run_wconv(W[3], 384, 192);
    run_gemm(B1, 384, 192);
    run_agg(B1, B0, b[3], out_h, 192, 1);      // out_h = h4

    // ---- Layer 5 (fp32, tiny) ----
    {
        dim3 grid(1, MT);
        sgemm_kernel<<<grid, 256>>>(out_h, W[4], B1, NNODES, 192, 5);
    }
    run_agg(B1, B0, b[4], out_o, 5, 0);        // out_o = final logits
}

// round 9
// speedup vs baseline: 2.4397x; 1.3032x over previous
#include <cuda_runtime.h>
#include <cuda_bf16.h>
#include <cstdint>

// ---------------------------------------------------------------------------
// Problem constants (fixed by the dataset)
// ---------------------------------------------------------------------------
#define NNODES 50000
#define MAXF   1536
#define MAXE   400000

// Scratch (allocation-free: __device__ globals)
__device__ float g_B0[(size_t)NNODES * MAXF];
__device__ float g_B1[(size_t)NNODES * MAXF];
__device__ __nv_bfloat16 g_Ahi[(size_t)NNODES * MAXF];
__device__ __nv_bfloat16 g_Alo[(size_t)NNODES * MAXF];
__device__ __nv_bfloat16 g_Whi[(size_t)MAXF * MAXF];
__device__ __nv_bfloat16 g_Wlo[(size_t)MAXF * MAXF];
__device__ float g_dinv[NNODES];
__device__ int   g_cnt[NNODES];
__device__ int   g_rowptr[NNODES + 1];
__device__ int   g_next[NNODES];
__device__ int   g_csrc[MAXE];
__device__ float g_cw[MAXE];

__device__ __forceinline__ uint32_t smem_u32(const void* p) {
    uint32_t a;
    asm("{ .reg .u64 t; cvta.to.shared.u64 t, %1; cvt.u32.u64 %0, t; }" : "=r"(a) : "l"(p));
    return a;
}

// ---------------------------------------------------------------------------
// CSR build
// ---------------------------------------------------------------------------
__global__ void zeroi_kernel(int* __restrict__ p, int n) {
    int i = blockIdx.x * blockDim.x + threadIdx.x;
    if (i < n) p[i] = 0;
}

__global__ void hist_kernel(const int* __restrict__ dst, int* __restrict__ cnt, int E) {
    int e = blockIdx.x * blockDim.x + threadIdx.x;
    if (e < E) atomicAdd(&cnt[dst[e]], 1);
}

__global__ void dinv_kernel(const int* __restrict__ cnt, float* __restrict__ dinv, int n) {
    int i = blockIdx.x * blockDim.x + threadIdx.x;
    if (i < n) dinv[i] = rsqrtf((float)cnt[i] + 1.0f);
}

// single-block exclusive scan over NNODES counts -> rowptr, next
__global__ __launch_bounds__(1024) void scan_kernel(const int* __restrict__ cnt,
                                                    int* __restrict__ rowptr,
                                                    int* __restrict__ nxt) {
    __shared__ int wsum[32];
    __shared__ int carry_s;
    const int tid = threadIdx.x, lane = tid & 31, wid = tid >> 5;
    if (tid == 0) carry_s = 0;
    __syncthreads();
    for (int start = 0; start < NNODES; start += 1024) {
        int i = start + tid;
        int v = (i < NNODES) ? cnt[i] : 0;
        int x = v;
        #pragma unroll
        for (int off = 1; off < 32; off <<= 1) {
            int t = __shfl_up_sync(0xFFFFFFFFu, x, off);
            if (lane >= off) x += t;
        }
        if (lane == 31) wsum[wid] = x;
        __syncthreads();
        if (wid == 0) {
            int y = wsum[lane];
            #pragma unroll
            for (int off = 1; off < 32; off <<= 1) {
                int t = __shfl_up_sync(0xFFFFFFFFu, y, off);
                if (lane >= off) y += t;
            }
            wsum[lane] = y;
        }
        __syncthreads();
        int woff = (wid > 0) ? wsum[wid - 1] : 0;
        int excl = x + woff - v;
        int c = carry_s;
        int total = wsum[31];
        if (i < NNODES) { rowptr[i] = c + excl; nxt[i] = c + excl; }
        __syncthreads();
        if (tid == 0) carry_s = c + total;
        __syncthreads();
    }
    if (threadIdx.x == 0) rowptr[NNODES] = carry_s;
}

__global__ void fill_kernel(const int* __restrict__ src, const int* __restrict__ dst,
                            const float* __restrict__ dinv, int* __restrict__ nxt,
                            int* __restrict__ csrc, float* __restrict__ cw, int E) {
    int e = blockIdx.x * blockDim.x + threadIdx.x;
    if (e >= E) return;
    int s = src[e], d = dst[e];
    int pos = atomicAdd(&nxt[d], 1);
    csrc[pos] = s;
    cw[pos] = dinv[s] * dinv[d];
}

// ---------------------------------------------------------------------------
// bf16 split helper
// ---------------------------------------------------------------------------
__device__ __forceinline__ void store_split4(__nv_bfloat16* hi, __nv_bfloat16* lo,
                                             size_t idx, float4 a) {
    __nv_bfloat16 h0 = __float2bfloat16(a.x), h1 = __float2bfloat16(a.y);
    __nv_bfloat16 h2 = __float2bfloat16(a.z), h3 = __float2bfloat16(a.w);
    __nv_bfloat16 l0 = __float2bfloat16(a.x - __bfloat162float(h0));
    __nv_bfloat16 l1 = __float2bfloat16(a.y - __bfloat162float(h1));
    __nv_bfloat16 l2 = __float2bfloat16(a.z - __bfloat162float(h2));
    __nv_bfloat16 l3 = __float2bfloat16(a.w - __bfloat162float(h3));
    __nv_bfloat162 hv0 = __halves2bfloat162(h0, h1), hv1 = __halves2bfloat162(h2, h3);
    __nv_bfloat162 lv0 = __halves2bfloat162(l0, l1), lv1 = __halves2bfloat162(l2, l3);
    uint2 hp, lp;
    hp.x = *(uint32_t*)&hv0; hp.y = *(uint32_t*)&hv1;
    lp.x = *(uint32_t*)&lv0; lp.y = *(uint32_t*)&lv1;
    *(uint2*)(hi + idx) = hp;
    *(uint2*)(lo + idx) = lp;
}

// ---------------------------------------------------------------------------
// Fused CSR gather: one node per block, blockDim = F/4.
//   acc = h[node]*dinv^2 (+bias); acc += sum_e h[csrc[e]] * cw[e];
//   optional relu; write fp32 (outf) and/or bf16 hi/lo split.
// ---------------------------------------------------------------------------
__global__ void gather_kernel(const float* __restrict__ h, const float* __restrict__ bias,
                              float* __restrict__ outf,
                              __nv_bfloat16* __restrict__ hi, __nv_bfloat16* __restrict__ lo,
                              int F, int do_relu)
{
    const int node = blockIdx.x;
    const int f0 = threadIdx.x * 4;
    const int rs = g_rowptr[node], re = g_rowptr[node + 1];
    const float di = g_dinv[node];
    const float d2 = di * di;

    float4 acc = *(const float4*)(h + (size_t)node * F + f0);
    acc.x *= d2; acc.y *= d2; acc.z *= d2; acc.w *= d2;
    if (bias) {
        float4 bb = *(const float4*)(bias + f0);
        acc.x += bb.x; acc.y += bb.y; acc.z += bb.z; acc.w += bb.w;
    }
    for (int e = rs; e < re; e++) {
        const int s = g_csrc[e];
        const float w = g_cw[e];
        float4 v = *(const float4*)(h + (size_t)s * F + f0);
        acc.x += v.x * w; acc.y += v.y * w; acc.z += v.z * w; acc.w += v.w * w;
    }
    if (do_relu) {
        acc.x = fmaxf(acc.x, 0.f); acc.y = fmaxf(acc.y, 0.f);
        acc.z = fmaxf(acc.z, 0.f); acc.w = fmaxf(acc.w, 0.f);
    }
    const size_t idx = (size_t)node * F + f0;
    if (outf) *(float4*)(outf + idx) = acc;
    if (hi) store_split4(hi, lo, idx, acc);
}

// scalar gather for F=5 (final layer): one thread per node
__global__ void gather_small_kernel(const float* __restrict__ h, const float* __restrict__ bias,
                                    float* __restrict__ outf, int F)
{
    int i = blockIdx.x * blockDim.x + threadIdx.x;
    if (i >= NNODES) return;
    const int rs = g_rowptr[i], re = g_rowptr[i + 1];
    const float di = g_dinv[i];
    const float d2 = di * di;
    float acc[8];
    for (int j = 0; j < F; j++) acc[j] = h[(size_t)i * F + j] * d2 + bias[j];
    for (int e = rs; e < re; e++) {
        const int s = g_csrc[e];
        const float w = g_cw[e];
        for (int j = 0; j < F; j++) acc[j] += h[(size_t)s * F + j] * w;
    }
    for (int j = 0; j < F; j++) outf[(size_t)i * F + j] = acc[j];
}

// ---------------------------------------------------------------------------
// W [K,N] fp32 -> Wt_hi/Wt_lo [N,K] bf16 (transpose + split)
// ---------------------------------------------------------------------------
__global__ void wconv_kernel(const float* __restrict__ W, __nv_bfloat16* __restrict__ Thi,
                             __nv_bfloat16* __restrict__ Tlo, int K, int N) {
    int idx = blockIdx.x * blockDim.x + threadIdx.x;
    if (idx >= K * N) return;
    int k = idx / N, n = idx - k * N;
    float w = W[idx];
    __nv_bfloat16 h = __float2bfloat16(w);
    Thi[(size_t)n * K + k] = h;
    Tlo[(size_t)n * K + k] = __float2bfloat16(w - __bfloat162float(h));
}

// relu(in + bias) -> bf16 hi/lo split (vectorized x4; F multiple of 4)
__global__ void biasact_split_kernel(const float* __restrict__ in, const float* __restrict__ bias,
                                     __nv_bfloat16* __restrict__ hi, __nv_bfloat16* __restrict__ lo,
                                     size_t n4, int F) {
    size_t i = (size_t)blockIdx.x * blockDim.x + threadIdx.x;
    if (i >= n4) return;
    size_t i4 = i * 4;
    int f = (int)(i4 % F);
    float4 v = *(const float4*)(in + i4);
    v.x = fmaxf(v.x + bias[f + 0], 0.f);
    v.y = fmaxf(v.y + bias[f + 1], 0.f);
    v.z = fmaxf(v.z + bias[f + 2], 0.f);
    v.w = fmaxf(v.w + bias[f + 3], 0.f);
    store_split4(hi, lo, i4, v);
}

// ---------------------------------------------------------------------------
// mma.sync bf16x3 GEMM: C[M,N] = Ahi*Whi + Alo*Whi + Ahi*Wlo   (unchanged)
// ---------------------------------------------------------------------------
#define TBK 32

__global__ __launch_bounds__(256, 2)
void gemm_mma_kernel(const __nv_bfloat16* __restrict__ Ahi, const __nv_bfloat16* __restrict__ Alo,
                     const __nv_bfloat16* __restrict__ Whi, const __nv_bfloat16* __restrict__ Wlo,
                     float* __restrict__ C, int M, int K, int N)
{
    __shared__ __align__(1024) __nv_bfloat16 As[2][128 * TBK];
    __shared__ __align__(1024) __nv_bfloat16 Bs[2][128 * TBK];

    const int tid  = threadIdx.x;
    const int lane = tid & 31;
    const int wid  = tid >> 5;
    const int wm   = (wid & 1) * 64;
    const int wn   = (wid >> 1) * 32;
    const int m0   = blockIdx.y * 128;
    const int n0   = blockIdx.x * 128;

    const int kc = K / TBK;
    const int KB = kc * 3;

    const uint32_t sA0 = smem_u32(&As[0][0]);
    const uint32_t sB0 = smem_u32(&Bs[0][0]);

    float acc[4][4][4];
    #pragma unroll
    for (int mi = 0; mi < 4; mi++)
        #pragma unroll
        for (int ni = 0; ni < 4; ni++)
            #pragma unroll
            for (int q = 0; q < 4; q++) acc[mi][ni][q] = 0.f;

    auto issue = [&](int kb, int buf) {
        const int pass = kb / kc;
        const int kk = (kb - pass * kc) * TBK;
        const __nv_bfloat16* Ap = (pass == 1) ? Alo : Ahi;
        const __nv_bfloat16* Bp = (pass == 2) ? Wlo : Whi;
        #pragma unroll
        for (int h = 0; h < 2; h++) {
            const int idx = tid + h * 256;
            const int r = idx >> 2, ch = idx & 3;
            const uint32_t soff = (uint32_t)r * 64 + (uint32_t)((ch ^ (r & 3)) * 16);
            {
                const int gr = m0 + r;
                const int ok = (gr < M) ? 16 : 0;
                const int grc = ok ? gr : 0;
                const void* ga = Ap + (size_t)grc * K + kk + ch * 8;
                uint32_t da = sA0 + (uint32_t)buf * 8192 + soff;
                asm volatile("cp.async.cg.shared.global [%0], [%1], 16, %2;"
                             :: "r"(da), "l"(ga), "r"(ok));
            }
            {
                const int gr = n0 + r;
                const int ok = (gr < N) ? 16 : 0;
                const int grc = ok ? gr : 0;
                const void* gb = Bp + (size_t)grc * K + kk + ch * 8;
                uint32_t db = sB0 + (uint32_t)buf * 8192 + soff;
                asm volatile("cp.async.cg.shared.global [%0], [%1], 16, %2;"
                             :: "r"(db), "l"(gb), "r"(ok));
            }
        }
        asm volatile("cp.async.commit_group;" ::: "memory");
    };

    auto compute = [&](int buf) {
        const uint32_t sA = sA0 + (uint32_t)buf * 8192;
        const uint32_t sB = sB0 + (uint32_t)buf * 8192;
        #pragma unroll
        for (int ks = 0; ks < 2; ks++) {
            uint32_t a[4][4];
            uint32_t b[4][2];
            #pragma unroll
            for (int mi = 0; mi < 4; mi++) {
                const int r = wm + mi * 16 + (lane & 15);
                const int ch = ks * 2 + (lane >> 4);
                const uint32_t addr = sA + (uint32_t)r * 64 + (uint32_t)((ch ^ (r & 3)) * 16);
                asm volatile("ldmatrix.sync.aligned.m8n8.x4.shared.b16 {%0,%1,%2,%3}, [%4];"
                             : "=r"(a[mi][0]), "=r"(a[mi][1]), "=r"(a[mi][2]), "=r"(a[mi][3])
                             : "r"(addr));
            }
            #pragma unroll
            for (int g = 0; g < 2; g++) {
                const int r = wn + g * 16 + (lane & 7) + ((lane >> 4) << 3);
                const int ch = ks * 2 + ((lane >> 3) & 1);
                const uint32_t addr = sB + (uint32_t)r * 64 + (uint32_t)((ch ^ (r & 3)) * 16);
                asm volatile("ldmatrix.sync.aligned.m8n8.x4.shared.b16 {%0,%1,%2,%3}, [%4];"
                             : "=r"(b[g * 2][0]), "=r"(b[g * 2][1]),
                               "=r"(b[g * 2 + 1][0]), "=r"(b[g * 2 + 1][1])
                             : "r"(addr));
            }
            #pragma unroll
            for (int mi = 0; mi < 4; mi++)
                #pragma unroll
                for (int ni = 0; ni < 4; ni++) {
                    asm volatile(
                        "mma.sync.aligned.m16n8k16.row.col.f32.bf16.bf16.f32 "
                        "{%0,%1,%2,%3}, {%4,%5,%6,%7}, {%8,%9}, {%0,%1,%2,%3};"
                        : "+f"(acc[mi][ni][0]), "+f"(acc[mi][ni][1]),
                          "+f"(acc[mi][ni][2]), "+f"(acc[mi][ni][3])
                        : "r"(a[mi][0]), "r"(a[mi][1]), "r"(a[mi][2]), "r"(a[mi][3]),
                          "r"(b[ni][0]), "r"(b[ni][1]));
                }
        }
    };

    issue(0, 0);
    for (int kb = 0; kb < KB; kb++) {
        const int buf = kb & 1;
        if (kb + 1 < KB) {
            issue(kb + 1, buf ^ 1);
            asm volatile("cp.async.wait_group 1;" ::: "memory");
        } else {
            asm volatile("cp.async.wait_group 0;" ::: "memory");
        }
        __syncthreads();
        compute(buf);
        __syncthreads();
    }

    #pragma unroll
    for (int mi = 0; mi < 4; mi++) {
        const int r0 = m0 + wm + mi * 16 + (lane >> 2);
        #pragma unroll
        for (int ni = 0; ni < 4; ni++) {
            const int col = n0 + wn + ni * 8 + 2 * (lane & 3);
            if (col >= N) continue;
            if (r0 < M) {
                float2 v = make_float2(acc[mi][ni][0], acc[mi][ni][1]);
                *(float2*)(C + (size_t)r0 * N + col) = v;
            }
            if (r0 + 8 < M) {
                float2 v = make_float2(acc[mi][ni][2], acc[mi][ni][3]);
                *(float2*)(C + (size_t)(r0 + 8) * N + col) = v;
            }
        }
    }
}

// ---------------------------------------------------------------------------
// fp32 SGEMM (tiny final layer, N=5)
// ---------------------------------------------------------------------------
#define BM 128
#define BN 128
#define BK 8
#define TM 8
#define TN 8

__global__ __launch_bounds__(256) void sgemm_kernel(
    const float* __restrict__ A, const float* __restrict__ B,
    float* __restrict__ C, int M, int K, int N)
{
    __shared__ __align__(16) float As[BK][BM];
    __shared__ __align__(16) float Bs[BK][BN];

    const int tid = threadIdx.x;
    const int block_row = blockIdx.y * BM;
    const int block_col = blockIdx.x * BN;
    const int tx = tid & 15, ty = tid >> 4;
    const int row0 = ty * TM, col0 = tx * TN;
    const int a_row = tid >> 1, a_k = (tid & 1) * 4;
    const int b_k = tid >> 5, b_col = (tid & 31) * 4;

    float acc[TM][TN];
    #pragma unroll
    for (int i = 0; i < TM; i++)
        #pragma unroll
        for (int j = 0; j < TN; j++) acc[i][j] = 0.f;

    for (int k0 = 0; k0 < K; k0 += BK) {
        float4 av = make_float4(0.f, 0.f, 0.f, 0.f);
        {
            int gr = block_row + a_row;
            if (gr < M) av = *(const float4*)(A + (size_t)gr * K + (k0 + a_k));
        }
        As[a_k + 0][a_row] = av.x;
        As[a_k + 1][a_row] = av.y;
        As[a_k + 2][a_row] = av.z;
        As[a_k + 3][a_row] = av.w;

        float4 bv = make_float4(0.f, 0.f, 0.f, 0.f);
        {
            int gc = block_col + b_col;
            const float* bp = B + (size_t)(k0 + b_k) * N;
            if ((N & 3) == 0) {
                if (gc + 3 < N) bv = *(const float4*)(bp + gc);
            } else {
                if (gc + 0 < N) bv.x = bp[gc + 0];
                if (gc + 1 < N) bv.y = bp[gc + 1];
                if (gc + 2 < N) bv.z = bp[gc + 2];
                if (gc + 3 < N) bv.w = bp[gc + 3];
            }
        }
        *(float4*)&Bs[b_k][b_col] = bv;

        __syncthreads();
        #pragma unroll
        for (int kk = 0; kk < BK; kk++) {
            float areg[TM], breg[TN];
            #pragma unroll
            for (int i = 0; i < TM; i++) areg[i] = As[kk][row0 + i];
            #pragma unroll
            for (int j = 0; j < TN; j++) breg[j] = Bs[kk][col0 + j];
            #pragma unroll
            for (int i = 0; i < TM; i++)
                #pragma unroll
                for (int j = 0; j < TN; j++)
                    acc[i][j] += areg[i] * breg[j];
        }
        __syncthreads();
    }

    #pragma unroll
    for (int i = 0; i < TM; i++) {
        int r = block_row + row0 + i;
        if (r >= M) continue;
        float* crow = C + (size_t)r * N;
        #pragma unroll
        for (int j = 0; j < TN; j++) {
            int c = block_col + col0 + j;
            if (c < N) crow[c] = acc[i][j];
        }
    }
}

// ---------------------------------------------------------------------------
// kernel_launch
// ---------------------------------------------------------------------------
extern "C" void kernel_launch(void* const* d_in, const int* in_sizes, int n_in,
                              void* d_out, int out_size)
{
    const float* x   = (const float*)d_in[0];
    const int*   ei  = (const int*)d_in[1];
    const int    E   = in_sizes[1] / 2;
    const int*   src = ei;
    const int*   dst = ei + E;

    const float* W[5];
    const float* b[5];
    for (int i = 0; i < 5; i++) {
        W[i] = (const float*)d_in[2 + 2 * i];
        b[i] = (const float*)d_in[3 + 2 * i];
    }

    float *B0, *B1, *dinv, *cw;
    int *cnt, *rowptr, *nxt, *csrc;
    __nv_bfloat16 *Ahi, *Alo, *Whi, *Wlo;
    cudaGetSymbolAddress((void**)&B0,     g_B0);
    cudaGetSymbolAddress((void**)&B1,     g_B1);
    cudaGetSymbolAddress((void**)&dinv,   g_dinv);
    cudaGetSymbolAddress((void**)&cnt,    g_cnt);
    cudaGetSymbolAddress((void**)&rowptr, g_rowptr);
    cudaGetSymbolAddress((void**)&nxt,    g_next);
    cudaGetSymbolAddress((void**)&csrc,   g_csrc);
    cudaGetSymbolAddress((void**)&cw,     g_cw);
    cudaGetSymbolAddress((void**)&Ahi,    g_Ahi);
    cudaGetSymbolAddress((void**)&Alo,    g_Alo);
    cudaGetSymbolAddress((void**)&Whi,    g_Whi);
    cudaGetSymbolAddress((void**)&Wlo,    g_Wlo);

    const int MT = (NNODES + 127) / 128;

    // ---- CSR build + dinv ----
    zeroi_kernel<<<(NNODES + 255) / 256, 256>>>(cnt, NNODES);
    hist_kernel<<<(E + 255) / 256, 256>>>(dst, cnt, E);
    dinv_kernel<<<(NNODES + 255) / 256, 256>>>(cnt, dinv, NNODES);
    scan_kernel<<<1, 1024>>>(cnt, rowptr, nxt);
    fill_kernel<<<(E + 255) / 256, 256>>>(src, dst, dinv, nxt, csrc, cw, E);

    float* out_h = (float*)d_out;                          // [N,192]
    float* out_o = (float*)d_out + (size_t)NNODES * 192;   // [N,5]

    auto run_wconv = [&](const float* Wp, int K, int N) {
        wconv_kernel<<<(K * N + 255) / 256, 256>>>(Wp, Whi, Wlo, K, N);
    };
    auto run_gemm = [&](float* C, int K, int N) {
        dim3 grid((N + 127) / 128, MT);
        gemm_mma_kernel<<<grid, 256>>>(Ahi, Alo, Whi, Wlo, C, NNODES, K, N);
    };

    // ---- Layer 1: aggregate FIRST on width 768 (A(xW) == (Ax)W) -> split ----
    gather_kernel<<<NNODES, 768 / 4>>>(x, nullptr, nullptr, Ahi, Alo, 768, 0);
    run_wconv(W[0], 768, 1536);
    run_gemm(B0, 768, 1536);                          // B0 = (Ahat x) W1
    {
        size_t n4 = (size_t)NNODES * 1536 / 4;
        biasact_split_kernel<<<(unsigned)((n4 + 255) / 256), 256>>>(
            B0, b[0], Ahi, Alo, n4, 1536);            // split(relu(B0 + b1)) = h1
    }

    // ---- Layer 2: GEMM (1536 -> 768) then fused gather+bias+relu+split ----
    run_wconv(W[1], 1536, 768);
    run_gemm(B1, 1536, 768);                          // B1 = h1 W2
    gather_kernel<<<NNODES, 768 / 4>>>(B1, b[1], nullptr, Ahi, Alo, 768, 1);

    // ---- Layer 3 ----
    run_wconv(W[2], 768, 384);
    run_gemm(B1, 768, 384);
    gather_kernel<<<NNODES, 384 / 4>>>(B1, b[2], nullptr, Ahi, Alo, 384, 1);

    // ---- Layer 4 (fp32 h4 straight into out_h; feeds fp32 layer-5 GEMM) ----
    run_wconv(W[3], 384, 192);
    run_gemm(B1, 384, 192);
    gather_kernel<<<NNODES, 192 / 4>>>(B1, b[3], out_h, nullptr, nullptr, 192, 1);

    // ---- Layer 5 (fp32, tiny) ----
    {
        dim3 grid(1, MT);
        sgemm_kernel<<<grid, 256>>>(out_h, W[4], B1, NNODES, 192, 5);
    }
    gather_small_kernel<<<(NNODES + 255) / 256, 256>>>(B1, b[4], out_o, 5);
}

// round 10
// speedup vs baseline: 3.0023x; 1.2306x over previous
#include <cuda_runtime.h>
#include <cuda_bf16.h>
#include <cstdint>

// ---------------------------------------------------------------------------
// Problem constants (fixed by the dataset)
// ---------------------------------------------------------------------------
#define NNODES 50000
#define MAXF   1536
#define MAXE   400000

// Scratch (allocation-free: __device__ globals)
__device__ float g_B0[(size_t)NNODES * MAXF];
__device__ float g_B1[(size_t)NNODES * MAXF];
__device__ __nv_bfloat16 g_Ahi[(size_t)NNODES * MAXF];
__device__ __nv_bfloat16 g_Alo[(size_t)NNODES * MAXF];
__device__ __nv_bfloat16 g_Whi[(size_t)MAXF * MAXF];
__device__ __nv_bfloat16 g_Wlo[(size_t)MAXF * MAXF];
__device__ float g_dinv[NNODES];
__device__ int   g_cnt[NNODES];
__device__ int   g_rowptr[NNODES + 1];
__device__ int   g_next[NNODES];
__device__ int   g_csrc[MAXE];
__device__ float g_cw[MAXE];

__device__ __forceinline__ uint32_t smem_u32(const void* p) {
    uint32_t a;
    asm("{ .reg .u64 t; cvta.to.shared.u64 t, %1; cvt.u32.u64 %0, t; }" : "=r"(a) : "l"(p));
    return a;
}

// ---------------------------------------------------------------------------
// CSR build
// ---------------------------------------------------------------------------
__global__ void zeroi_kernel(int* __restrict__ p, int n) {
    int i = blockIdx.x * blockDim.x + threadIdx.x;
    if (i < n) p[i] = 0;
}

__global__ void hist_kernel(const int* __restrict__ dst, int* __restrict__ cnt, int E) {
    int e = blockIdx.x * blockDim.x + threadIdx.x;
    if (e < E) atomicAdd(&cnt[dst[e]], 1);
}

__global__ void dinv_kernel(const int* __restrict__ cnt, float* __restrict__ dinv, int n) {
    int i = blockIdx.x * blockDim.x + threadIdx.x;
    if (i < n) dinv[i] = rsqrtf((float)cnt[i] + 1.0f);
}

// single-block exclusive scan over NNODES counts -> rowptr, next
__global__ __launch_bounds__(1024) void scan_kernel(const int* __restrict__ cnt,
                                                    int* __restrict__ rowptr,
                                                    int* __restrict__ nxt) {
    __shared__ int wsum[32];
    __shared__ int carry_s;
    const int tid = threadIdx.x, lane = tid & 31, wid = tid >> 5;
    if (tid == 0) carry_s = 0;
    __syncthreads();
    for (int start = 0; start < NNODES; start += 1024) {
        int i = start + tid;
        int v = (i < NNODES) ? cnt[i] : 0;
        int x = v;
        #pragma unroll
        for (int off = 1; off < 32; off <<= 1) {
            int t = __shfl_up_sync(0xFFFFFFFFu, x, off);
            if (lane >= off) x += t;
        }
        if (lane == 31) wsum[wid] = x;
        __syncthreads();
        if (wid == 0) {
            int y = wsum[lane];
            #pragma unroll
            for (int off = 1; off < 32; off <<= 1) {
                int t = __shfl_up_sync(0xFFFFFFFFu, y, off);
                if (lane >= off) y += t;
            }
            wsum[lane] = y;
        }
        __syncthreads();
        int woff = (wid > 0) ? wsum[wid - 1] : 0;
        int excl = x + woff - v;
        int c = carry_s;
        int total = wsum[31];
        if (i < NNODES) { rowptr[i] = c + excl; nxt[i] = c + excl; }
        __syncthreads();
        if (tid == 0) carry_s = c + total;
        __syncthreads();
    }
    if (threadIdx.x == 0) rowptr[NNODES] = carry_s;
}

__global__ void fill_kernel(const int* __restrict__ src, const int* __restrict__ dst,
                            const float* __restrict__ dinv, int* __restrict__ nxt,
                            int* __restrict__ csrc, float* __restrict__ cw, int E) {
    int e = blockIdx.x * blockDim.x + threadIdx.x;
    if (e >= E) return;
    int s = src[e], d = dst[e];
    int pos = atomicAdd(&nxt[d], 1);
    csrc[pos] = s;
    cw[pos] = dinv[s] * dinv[d];
}

// ---------------------------------------------------------------------------
// bf16 split helper
// ---------------------------------------------------------------------------
__device__ __forceinline__ void store_split4(__nv_bfloat16* hi, __nv_bfloat16* lo,
                                             size_t idx, float4 a) {
    __nv_bfloat16 h0 = __float2bfloat16(a.x), h1 = __float2bfloat16(a.y);
    __nv_bfloat16 h2 = __float2bfloat16(a.z), h3 = __float2bfloat16(a.w);
    __nv_bfloat16 l0 = __float2bfloat16(a.x - __bfloat162float(h0));
    __nv_bfloat16 l1 = __float2bfloat16(a.y - __bfloat162float(h1));
    __nv_bfloat16 l2 = __float2bfloat16(a.z - __bfloat162float(h2));
    __nv_bfloat16 l3 = __float2bfloat16(a.w - __bfloat162float(h3));
    __nv_bfloat162 hv0 = __halves2bfloat162(h0, h1), hv1 = __halves2bfloat162(h2, h3);
    __nv_bfloat162 lv0 = __halves2bfloat162(l0, l1), lv1 = __halves2bfloat162(l2, l3);
    uint2 hp, lp;
    hp.x = *(uint32_t*)&hv0; hp.y = *(uint32_t*)&hv1;
    lp.x = *(uint32_t*)&lv0; lp.y = *(uint32_t*)&lv1;
    *(uint2*)(hi + idx) = hp;
    *(uint2*)(lo + idx) = lp;
}

// ---------------------------------------------------------------------------
// Fused CSR gather: one node per block, blockDim = F/4.
// ---------------------------------------------------------------------------
__global__ void gather_kernel(const float* __restrict__ h, const float* __restrict__ bias,
                              float* __restrict__ outf,
                              __nv_bfloat16* __restrict__ hi, __nv_bfloat16* __restrict__ lo,
                              int F, int do_relu)
{
    const int node = blockIdx.x;
    const int f0 = threadIdx.x * 4;
    const int rs = g_rowptr[node], re = g_rowptr[node + 1];
    const float di = g_dinv[node];
    const float d2 = di * di;

    float4 acc = *(const float4*)(h + (size_t)node * F + f0);
    acc.x *= d2; acc.y *= d2; acc.z *= d2; acc.w *= d2;
    if (bias) {
        float4 bb = *(const float4*)(bias + f0);
        acc.x += bb.x; acc.y += bb.y; acc.z += bb.z; acc.w += bb.w;
    }
    for (int e = rs; e < re; e++) {
        const int s = g_csrc[e];
        const float w = g_cw[e];
        float4 v = *(const float4*)(h + (size_t)s * F + f0);
        acc.x += v.x * w; acc.y += v.y * w; acc.z += v.z * w; acc.w += v.w * w;
    }
    if (do_relu) {
        acc.x = fmaxf(acc.x, 0.f); acc.y = fmaxf(acc.y, 0.f);
        acc.z = fmaxf(acc.z, 0.f); acc.w = fmaxf(acc.w, 0.f);
    }
    const size_t idx = (size_t)node * F + f0;
    if (outf) *(float4*)(outf + idx) = acc;
    if (hi) store_split4(hi, lo, idx, acc);
}

// scalar gather for F=5 (final layer): one thread per node
__global__ void gather_small_kernel(const float* __restrict__ h, const float* __restrict__ bias,
                                    float* __restrict__ outf, int F)
{
    int i = blockIdx.x * blockDim.x + threadIdx.x;
    if (i >= NNODES) return;
    const int rs = g_rowptr[i], re = g_rowptr[i + 1];
    const float di = g_dinv[i];
    const float d2 = di * di;
    float acc[8];
    for (int j = 0; j < F; j++) acc[j] = h[(size_t)i * F + j] * d2 + bias[j];
    for (int e = rs; e < re; e++) {
        const int s = g_csrc[e];
        const float w = g_cw[e];
        for (int j = 0; j < F; j++) acc[j] += h[(size_t)s * F + j] * w;
    }
    for (int j = 0; j < F; j++) outf[(size_t)i * F + j] = acc[j];
}

// ---------------------------------------------------------------------------
// W [K,N] fp32 -> Wt_hi/Wt_lo [N,K] bf16 (transpose + split)
// ---------------------------------------------------------------------------
__global__ void wconv_kernel(const float* __restrict__ W, __nv_bfloat16* __restrict__ Thi,
                             __nv_bfloat16* __restrict__ Tlo, int K, int N) {
    int idx = blockIdx.x * blockDim.x + threadIdx.x;
    if (idx >= K * N) return;
    int k = idx / N, n = idx - k * N;
    float w = W[idx];
    __nv_bfloat16 h = __float2bfloat16(w);
    Thi[(size_t)n * K + k] = h;
    Tlo[(size_t)n * K + k] = __float2bfloat16(w - __bfloat162float(h));
}

// relu(in + bias) -> bf16 hi/lo split
__global__ void biasact_split_kernel(const float* __restrict__ in, const float* __restrict__ bias,
                                     __nv_bfloat16* __restrict__ hi, __nv_bfloat16* __restrict__ lo,
                                     size_t n4, int F) {
    size_t i = (size_t)blockIdx.x * blockDim.x + threadIdx.x;
    if (i >= n4) return;
    size_t i4 = i * 4;
    int f = (int)(i4 % F);
    float4 v = *(const float4*)(in + i4);
    v.x = fmaxf(v.x + bias[f + 0], 0.f);
    v.y = fmaxf(v.y + bias[f + 1], 0.f);
    v.z = fmaxf(v.z + bias[f + 2], 0.f);
    v.w = fmaxf(v.w + bias[f + 3], 0.f);
    store_split4(hi, lo, i4, v);
}

// ---------------------------------------------------------------------------
// Fused bf16x3 GEMM: C = Ahi*Whi + Alo*Whi + Ahi*Wlo, all 3 passes per k-chunk.
//   A*: [M,K] bf16 row-major.  W*: [N,K] bf16 row-major (= W^T, K-major).
//   Block tile 128 x BNT x 32. 256 thr = 8 warps (2m x 4n), warp tile 64 x BNT/4.
//   3-stage cp.async pipeline; per chunk smem holds {Ahi, Alo, Whi, Wlo} tiles.
// ---------------------------------------------------------------------------
template<int BNT>
__global__ __launch_bounds__(256)
void gemm3_kernel(const __nv_bfloat16* __restrict__ Ahi, const __nv_bfloat16* __restrict__ Alo,
                  const __nv_bfloat16* __restrict__ Whi, const __nv_bfloat16* __restrict__ Wlo,
                  float* __restrict__ C, int M, int K, int N)
{
    constexpr int NW = BNT / 32;                 // n8 groups per warp
    constexpr int STAGE = (256 + 2 * BNT) * 64;  // bytes per stage
    constexpr int OFF_ALO = 128 * 64;
    constexpr int OFF_BHI = 256 * 64;
    constexpr int OFF_BLO = 256 * 64 + BNT * 64;
    constexpr int NCH = (256 + 2 * BNT) * 4 / 256;  // 16B chunks per thread per stage

    extern __shared__ __align__(1024) char smem[];
    const uint32_t sbase = smem_u32(smem);

    const int tid = threadIdx.x, lane = tid & 31, wid = tid >> 5;
    const int wm = (wid & 1) * 64;
    const int wn = (wid >> 1) * (BNT / 4);
    const int m0 = blockIdx.y * 128;
    const int n0 = blockIdx.x * BNT;
    const int kc = K / 32;

    float acc[4][NW][4];
    #pragma unroll
    for (int mi = 0; mi < 4; mi++)
        #pragma unroll
        for (int ni = 0; ni < NW; ni++)
            #pragma unroll
            for (int q = 0; q < 4; q++) acc[mi][ni][q] = 0.f;

    auto issue = [&](int c) {
        const int st = c % 3;
        const int kk = c * 32;
        const uint32_t dstb = sbase + (uint32_t)st * STAGE;
        #pragma unroll
        for (int h = 0; h < NCH; h++) {
            const int idx = tid + h * 256;
            const int r_all = idx >> 2, ch = idx & 3;
            const __nv_bfloat16* base;
            uint32_t roff;
            int r, grow, limit;
            if (h < 2)                  { base = Ahi; roff = 0;       r = r_all;             grow = m0 + r; limit = M; }
            else if (h < 4)             { base = Alo; roff = OFF_ALO; r = r_all - 128;       grow = m0 + r; limit = M; }
            else if (h < 4 + BNT / 64)  { base = Whi; roff = OFF_BHI; r = r_all - 256;       grow = n0 + r; limit = N; }
            else                        { base = Wlo; roff = OFF_BLO; r = r_all - 256 - BNT; grow = n0 + r; limit = N; }
            const int ok = (grow < limit) ? 16 : 0;
            const int grc = ok ? grow : 0;
            const void* g = base + (size_t)grc * K + kk + ch * 8;
            const uint32_t d = dstb + roff + (uint32_t)r * 64 + (uint32_t)((ch ^ (r & 3)) * 16);
            asm volatile("cp.async.cg.shared.global [%0], [%1], 16, %2;"
                         :: "r"(d), "l"(g), "r"(ok));
        }
        asm volatile("cp.async.commit_group;" ::: "memory");
    };

    auto compute = [&](int st) {
        const uint32_t sAh = sbase + (uint32_t)st * STAGE;
        const uint32_t sAl = sAh + OFF_ALO;
        const uint32_t sBh = sAh + OFF_BHI;
        const uint32_t sBl = sAh + OFF_BLO;
        #pragma unroll
        for (int ks = 0; ks < 2; ks++) {
            uint32_t ah[4][4], al[4][4], b[NW][2];
            #pragma unroll
            for (int mi = 0; mi < 4; mi++) {
                const int r = wm + mi * 16 + (lane & 15);
                const int ch = ks * 2 + (lane >> 4);
                const uint32_t off = (uint32_t)r * 64 + (uint32_t)((ch ^ (r & 3)) * 16);
                asm volatile("ldmatrix.sync.aligned.m8n8.x4.shared.b16 {%0,%1,%2,%3}, [%4];"
                             : "=r"(ah[mi][0]), "=r"(ah[mi][1]), "=r"(ah[mi][2]), "=r"(ah[mi][3])
                             : "r"(sAh + off));
                asm volatile("ldmatrix.sync.aligned.m8n8.x4.shared.b16 {%0,%1,%2,%3}, [%4];"
                             : "=r"(al[mi][0]), "=r"(al[mi][1]), "=r"(al[mi][2]), "=r"(al[mi][3])
                             : "r"(sAl + off));
            }
            // Whi fragments
            #pragma unroll
            for (int g2 = 0; g2 < NW / 2; g2++) {
                const int r = wn + g2 * 16 + (lane & 7) + ((lane >> 4) << 3);
                const int ch = ks * 2 + ((lane >> 3) & 1);
                const uint32_t off = (uint32_t)r * 64 + (uint32_t)((ch ^ (r & 3)) * 16);
                asm volatile("ldmatrix.sync.aligned.m8n8.x4.shared.b16 {%0,%1,%2,%3}, [%4];"
                             : "=r"(b[g2 * 2][0]), "=r"(b[g2 * 2][1]),
                               "=r"(b[g2 * 2 + 1][0]), "=r"(b[g2 * 2 + 1][1])
                             : "r"(sBh + off));
            }
            #pragma unroll
            for (int mi = 0; mi < 4; mi++)
                #pragma unroll
                for (int ni = 0; ni < NW; ni++) {
                    asm volatile(
                        "mma.sync.aligned.m16n8k16.row.col.f32.bf16.bf16.f32 "
                        "{%0,%1,%2,%3}, {%4,%5,%6,%7}, {%8,%9}, {%0,%1,%2,%3};"
                        : "+f"(acc[mi][ni][0]), "+f"(acc[mi][ni][1]),
                          "+f"(acc[mi][ni][2]), "+f"(acc[mi][ni][3])
                        : "r"(ah[mi][0]), "r"(ah[mi][1]), "r"(ah[mi][2]), "r"(ah[mi][3]),
                          "r"(b[ni][0]), "r"(b[ni][1]));
                }
            #pragma unroll
            for (int mi = 0; mi < 4; mi++)
                #pragma unroll
                for (int ni = 0; ni < NW; ni++) {
                    asm volatile(
                        "mma.sync.aligned.m16n8k16.row.col.f32.bf16.bf16.f32 "
                        "{%0,%1,%2,%3}, {%4,%5,%6,%7}, {%8,%9}, {%0,%1,%2,%3};"
                        : "+f"(acc[mi][ni][0]), "+f"(acc[mi][ni][1]),
                          "+f"(acc[mi][ni][2]), "+f"(acc[mi][ni][3])
                        : "r"(al[mi][0]), "r"(al[mi][1]), "r"(al[mi][2]), "r"(al[mi][3]),
                          "r"(b[ni][0]), "r"(b[ni][1]));
                }
            // Wlo fragments (reuse b regs)
            #pragma unroll
            for (int g2 = 0; g2 < NW / 2; g2++) {
                const int r = wn + g2 * 16 + (lane & 7) + ((lane >> 4) << 3);
                const int ch = ks * 2 + ((lane >> 3) & 1);
                const uint32_t off = (uint32_t)r * 64 + (uint32_t)((ch ^ (r & 3)) * 16);
                asm volatile("ldmatrix.sync.aligned.m8n8.x4.shared.b16 {%0,%1,%2,%3}, [%4];"
                             : "=r"(b[g2 * 2][0]), "=r"(b[g2 * 2][1]),
                               "=r"(b[g2 * 2 + 1][0]), "=r"(b[g2 * 2 + 1][1])
                             : "r"(sBl + off));
            }
            #pragma unroll
            for (int mi = 0; mi < 4; mi++)
                #pragma unroll
                for (int ni = 0; ni < NW; ni++) {
                    asm volatile(
                        "mma.sync.aligned.m16n8k16.row.col.f32.bf16.bf16.f32 "
                        "{%0,%1,%2,%3}, {%4,%5,%6,%7}, {%8,%9}, {%0,%1,%2,%3};"
                        : "+f"(acc[mi][ni][0]), "+f"(acc[mi][ni][1]),
                          "+f"(acc[mi][ni][2]), "+f"(acc[mi][ni][3])
                        : "r"(ah[mi][0]), "r"(ah[mi][1]), "r"(ah[mi][2]), "r"(ah[mi][3]),
                          "r"(b[ni][0]), "r"(b[ni][1]));
                }
        }
    };

    issue(0);
    if (kc > 1) issue(1);
    for (int c = 0; c < kc; c++) {
        if (c + 2 < kc) issue(c + 2);
        if (c + 1 < kc) {
            asm volatile("cp.async.wait_group 1;" ::: "memory");
        } else {
            asm volatile("cp.async.wait_group 0;" ::: "memory");
        }
        __syncthreads();
        compute(c % 3);
        __syncthreads();
    }

    // epilogue: acc -> C (float2; col even, N % 8 == 0)
    #pragma unroll
    for (int mi = 0; mi < 4; mi++) {
        const int r0 = m0 + wm + mi * 16 + (lane >> 2);
        #pragma unroll
        for (int ni = 0; ni < NW; ni++) {
            const int col = n0 + wn + ni * 8 + 2 * (lane & 3);
            if (col >= N) continue;
            if (r0 < M) {
                float2 v = make_float2(acc[mi][ni][0], acc[mi][ni][1]);
                *(float2*)(C + (size_t)r0 * N + col) = v;
            }
            if (r0 + 8 < M) {
                float2 v = make_float2(acc[mi][ni][2], acc[mi][ni][3]);
                *(float2*)(C + (size_t)(r0 + 8) * N + col) = v;
            }
        }
    }
}

// ---------------------------------------------------------------------------
// fp32 SGEMM (tiny final layer, N=5)
// ---------------------------------------------------------------------------
#define BM 128
#define BN 128
#define BK 8
#define TM 8
#define TN 8

__global__ __launch_bounds__(256) void sgemm_kernel(
    const float* __restrict__ A, const float* __restrict__ B,
    float* __restrict__ C, int M, int K, int N)
{
    __shared__ __align__(16) float As[BK][BM];
    __shared__ __align__(16) float Bs[BK][BN];

    const int tid = threadIdx.x;
    const int block_row = blockIdx.y * BM;
    const int block_col = blockIdx.x * BN;
    const int tx = tid & 15, ty = tid >> 4;
    const int row0 = ty * TM, col0 = tx * TN;
    const int a_row = tid >> 1, a_k = (tid & 1) * 4;
    const int b_k = tid >> 5, b_col = (tid & 31) * 4;

    float acc[TM][TN];
    #pragma unroll
    for (int i = 0; i < TM; i++)
        #pragma unroll
        for (int j = 0; j < TN; j++) acc[i][j] = 0.f;

    for (int k0 = 0; k0 < K; k0 += BK) {
        float4 av = make_float4(0.f, 0.f, 0.f, 0.f);
        {
            int gr = block_row + a_row;
            if (gr < M) av = *(const float4*)(A + (size_t)gr * K + (k0 + a_k));
        }
        As[a_k + 0][a_row] = av.x;
        As[a_k + 1][a_row] = av.y;
        As[a_k + 2][a_row] = av.z;
        As[a_k + 3][a_row] = av.w;

        float4 bv = make_float4(0.f, 0.f, 0.f, 0.f);
        {
            int gc = block_col + b_col;
            const float* bp = B + (size_t)(k0 + b_k) * N;
            if ((N & 3) == 0) {
                if (gc + 3 < N) bv = *(const float4*)(bp + gc);
            } else {
                if (gc + 0 < N) bv.x = bp[gc + 0];
                if (gc + 1 < N) bv.y = bp[gc + 1];
                if (gc + 2 < N) bv.z = bp[gc + 2];
                if (gc + 3 < N) bv.w = bp[gc + 3];
            }
        }
        *(float4*)&Bs[b_k][b_col] = bv;

        __syncthreads();
        #pragma unroll
        for (int kk = 0; kk < BK; kk++) {
            float areg[TM], breg[TN];
            #pragma unroll
            for (int i = 0; i < TM; i++) areg[i] = As[kk][row0 + i];
            #pragma unroll
            for (int j = 0; j < TN; j++) breg[j] = Bs[kk][col0 + j];
            #pragma unroll
            for (int i = 0; i < TM; i++)
                #pragma unroll
                for (int j = 0; j < TN; j++)
                    acc[i][j] += areg[i] * breg[j];
        }
        __syncthreads();
    }

    #pragma unroll
    for (int i = 0; i < TM; i++) {
        int r = block_row + row0 + i;
        if (r >= M) continue;
        float* crow = C + (size_t)r * N;
        #pragma unroll
        for (int j = 0; j < TN; j++) {
            int c = block_col + col0 + j;
            if (c < N) crow[c] = acc[i][j];
        }
    }
}

// ---------------------------------------------------------------------------
// kernel_launch
// ---------------------------------------------------------------------------
extern "C" void kernel_launch(void* const* d_in, const int* in_sizes, int n_in,
                              void* d_out, int out_size)
{
    const float* x   = (const float*)d_in[0];
    const int*   ei  = (const int*)d_in[1];
    const int    E   = in_sizes[1] / 2;
    const int*   src = ei;
    const int*   dst = ei + E;

    const float* W[5];
    const float* b[5];
    for (int i = 0; i < 5; i++) {
        W[i] = (const float*)d_in[2 + 2 * i];
        b[i] = (const float*)d_in[3 + 2 * i];
    }

    float *B0, *B1, *dinv, *cw;
    int *cnt, *rowptr, *nxt, *csrc;
    __nv_bfloat16 *Ahi, *Alo, *Whi, *Wlo;
    cudaGetSymbolAddress((void**)&B0,     g_B0);
    cudaGetSymbolAddress((void**)&B1,     g_B1);
    cudaGetSymbolAddress((void**)&dinv,   g_dinv);
    cudaGetSymbolAddress((void**)&cnt,    g_cnt);
    cudaGetSymbolAddress((void**)&rowptr, g_rowptr);
    cudaGetSymbolAddress((void**)&nxt,    g_next);
    cudaGetSymbolAddress((void**)&csrc,   g_csrc);
    cudaGetSymbolAddress((void**)&cw,     g_cw);
    cudaGetSymbolAddress((void**)&Ahi,    g_Ahi);
    cudaGetSymbolAddress((void**)&Alo,    g_Alo);
    cudaGetSymbolAddress((void**)&Whi,    g_Whi);
    cudaGetSymbolAddress((void**)&Wlo,    g_Wlo);

    const int MT = (NNODES + 127) / 128;
    constexpr int SMEM256 = (256 + 512) * 64 * 3;   // 147456
    constexpr int SMEM128 = (256 + 256) * 64 * 3;   // 98304
    static bool attr_set = false;
    if (!attr_set) {
        cudaFuncSetAttribute(gemm3_kernel<256>, cudaFuncAttributeMaxDynamicSharedMemorySize, SMEM256);
        cudaFuncSetAttribute(gemm3_kernel<128>, cudaFuncAttributeMaxDynamicSharedMemorySize, SMEM128);
        attr_set = true;
    }

    // ---- CSR build + dinv ----
    zeroi_kernel<<<(NNODES + 255) / 256, 256>>>(cnt, NNODES);
    hist_kernel<<<(E + 255) / 256, 256>>>(dst, cnt, E);
    dinv_kernel<<<(NNODES + 255) / 256, 256>>>(cnt, dinv, NNODES);
    scan_kernel<<<1, 1024>>>(cnt, rowptr, nxt);
    fill_kernel<<<(E + 255) / 256, 256>>>(src, dst, dinv, nxt, csrc, cw, E);

    float* out_h = (float*)d_out;                          // [N,192]
    float* out_o = (float*)d_out + (size_t)NNODES * 192;   // [N,5]

    auto run_wconv = [&](const float* Wp, int K, int N) {
        wconv_kernel<<<(K * N + 255) / 256, 256>>>(Wp, Whi, Wlo, K, N);
    };
    auto run_gemm = [&](float* C, int K, int N) {
        if (N % 256 == 0) {
            dim3 grid(N / 256, MT);
            gemm3_kernel<256><<<grid, 256, SMEM256>>>(Ahi, Alo, Whi, Wlo, C, NNODES, K, N);
        } else {
            dim3 grid((N + 127) / 128, MT);
            gemm3_kernel<128><<<grid, 256, SMEM128>>>(Ahi, Alo, Whi, Wlo, C, NNODES, K, N);
        }
    };

    // ---- Layer 1: aggregate FIRST on width 768 (A(xW) == (Ax)W) -> split ----
    gather_kernel<<<NNODES, 768 / 4>>>(x, nullptr, nullptr, Ahi, Alo, 768, 0);
    run_wconv(W[0], 768, 1536);
    run_gemm(B0, 768, 1536);                          // B0 = (Ahat x) W1
    {
        size_t n4 = (size_t)NNODES * 1536 / 4;
        biasact_split_kernel<<<(unsigned)((n4 + 255) / 256), 256>>>(
            B0, b[0], Ahi, Alo, n4, 1536);            // split(relu(B0 + b1)) = h1
    }

    // ---- Layer 2: GEMM (1536 -> 768) then fused gather+bias+relu+split ----
    run_wconv(W[1], 1536, 768);
    run_gemm(B1, 1536, 768);                          // B1 = h1 W2
    gather_kernel<<<NNODES, 768 / 4>>>(B1, b[1], nullptr, Ahi, Alo, 768, 1);

    // ---- Layer 3 ----
    run_wconv(W[2], 768, 384);
    run_gemm(B1, 768, 384);
    gather_kernel<<<NNODES, 384 / 4>>>(B1, b[2], nullptr, Ahi, Alo, 384, 1);

    // ---- Layer 4 (fp32 h4 straight into out_h; feeds fp32 layer-5 GEMM) ----
    run_wconv(W[3], 384, 192);
    run_gemm(B1, 384, 192);
    gather_kernel<<<NNODES, 192 / 4>>>(B1, b[3], out_h, nullptr, nullptr, 192, 1);

    // ---- Layer 5 (fp32, tiny) ----
    {
        dim3 grid(1, MT);
        sgemm_kernel<<<grid, 256>>>(out_h, W[4], B1, NNODES, 192, 5);
    }
    gather_small_kernel<<<(NNODES + 255) / 256, 256>>>(B1, b[4], out_o, 5);
}

// round 11
// speedup vs baseline: 3.2771x; 1.0915x over previous
#include <cuda_runtime.h>
#include <cuda_bf16.h>
#include <cstdint>

// ---------------------------------------------------------------------------
// Problem constants (fixed by the dataset)
// ---------------------------------------------------------------------------
#define NNODES 50000
#define MAXF   1536
#define MAXE   400000

// Scratch (allocation-free: __device__ globals)
__device__ float g_B0[(size_t)NNODES * MAXF];
__device__ float g_B1[(size_t)NNODES * MAXF];
__device__ __nv_bfloat16 g_Ahi[(size_t)NNODES * MAXF];
__device__ __nv_bfloat16 g_Alo[(size_t)NNODES * MAXF];
__device__ __nv_bfloat16 g_Bhi[(size_t)NNODES * MAXF];
__device__ __nv_bfloat16 g_Blo[(size_t)NNODES * MAXF];
__device__ __nv_bfloat16 g_Whi[(size_t)MAXF * MAXF];
__device__ __nv_bfloat16 g_Wlo[(size_t)MAXF * MAXF];
__device__ float g_dinv[NNODES];
__device__ int   g_cnt[NNODES];
__device__ int   g_rowptr[NNODES + 1];
__device__ int   g_next[NNODES];
__device__ int   g_csrc[MAXE];
__device__ float g_cw[MAXE];

__device__ __forceinline__ uint32_t smem_u32(const void* p) {
    uint32_t a;
    asm("{ .reg .u64 t; cvta.to.shared.u64 t, %1; cvt.u32.u64 %0, t; }" : "=r"(a) : "l"(p));
    return a;
}

// ---------------------------------------------------------------------------
// CSR build
// ---------------------------------------------------------------------------
__global__ void zeroi_kernel(int* __restrict__ p, int n) {
    int i = blockIdx.x * blockDim.x + threadIdx.x;
    if (i < n) p[i] = 0;
}

__global__ void hist_kernel(const int* __restrict__ dst, int* __restrict__ cnt, int E) {
    int e = blockIdx.x * blockDim.x + threadIdx.x;
    if (e < E) atomicAdd(&cnt[dst[e]], 1);
}

// single-block exclusive scan over NNODES counts -> rowptr, next (+ dinv)
__global__ __launch_bounds__(1024) void scan_kernel(const int* __restrict__ cnt,
                                                    int* __restrict__ rowptr,
                                                    int* __restrict__ nxt,
                                                    float* __restrict__ dinv) {
    __shared__ int wsum[32];
    __shared__ int carry_s;
    const int tid = threadIdx.x, lane = tid & 31, wid = tid >> 5;
    if (tid == 0) carry_s = 0;
    __syncthreads();
    for (int start = 0; start < NNODES; start += 1024) {
        int i = start + tid;
        int v = (i < NNODES) ? cnt[i] : 0;
        if (i < NNODES) dinv[i] = rsqrtf((float)v + 1.0f);
        int x = v;
        #pragma unroll
        for (int off = 1; off < 32; off <<= 1) {
            int t = __shfl_up_sync(0xFFFFFFFFu, x, off);
            if (lane >= off) x += t;
        }
        if (lane == 31) wsum[wid] = x;
        __syncthreads();
        if (wid == 0) {
            int y = wsum[lane];
            #pragma unroll
            for (int off = 1; off < 32; off <<= 1) {
                int t = __shfl_up_sync(0xFFFFFFFFu, y, off);
                if (lane >= off) y += t;
            }
            wsum[lane] = y;
        }
        __syncthreads();
        int woff = (wid > 0) ? wsum[wid - 1] : 0;
        int excl = x + woff - v;
        int c = carry_s;
        int total = wsum[31];
        if (i < NNODES) { rowptr[i] = c + excl; nxt[i] = c + excl; }
        __syncthreads();
        if (tid == 0) carry_s = c + total;
        __syncthreads();
    }
    if (threadIdx.x == 0) rowptr[NNODES] = carry_s;
}

__global__ void fill_kernel(const int* __restrict__ src, const int* __restrict__ dst,
                            const float* __restrict__ dinv, int* __restrict__ nxt,
                            int* __restrict__ csrc, float* __restrict__ cw, int E) {
    int e = blockIdx.x * blockDim.x + threadIdx.x;
    if (e >= E) return;
    int s = src[e], d = dst[e];
    int pos = atomicAdd(&nxt[d], 1);
    csrc[pos] = s;
    cw[pos] = dinv[s] * dinv[d];
}

// ---------------------------------------------------------------------------
// bf16 split helpers
// ---------------------------------------------------------------------------
__device__ __forceinline__ void store_split4(__nv_bfloat16* hi, __nv_bfloat16* lo,
                                             size_t idx, float4 a) {
    __nv_bfloat16 h0 = __float2bfloat16(a.x), h1 = __float2bfloat16(a.y);
    __nv_bfloat16 h2 = __float2bfloat16(a.z), h3 = __float2bfloat16(a.w);
    __nv_bfloat16 l0 = __float2bfloat16(a.x - __bfloat162float(h0));
    __nv_bfloat16 l1 = __float2bfloat16(a.y - __bfloat162float(h1));
    __nv_bfloat16 l2 = __float2bfloat16(a.z - __bfloat162float(h2));
    __nv_bfloat16 l3 = __float2bfloat16(a.w - __bfloat162float(h3));
    __nv_bfloat162 hv0 = __halves2bfloat162(h0, h1), hv1 = __halves2bfloat162(h2, h3);
    __nv_bfloat162 lv0 = __halves2bfloat162(l0, l1), lv1 = __halves2bfloat162(l2, l3);
    uint2 hp, lp;
    hp.x = *(uint32_t*)&hv0; hp.y = *(uint32_t*)&hv1;
    lp.x = *(uint32_t*)&lv0; lp.y = *(uint32_t*)&lv1;
    *(uint2*)(hi + idx) = hp;
    *(uint2*)(lo + idx) = lp;
}

__device__ __forceinline__ void store_split2(__nv_bfloat16* hi, __nv_bfloat16* lo,
                                             size_t idx, float a, float b) {
    __nv_bfloat16 h0 = __float2bfloat16(a), h1 = __float2bfloat16(b);
    __nv_bfloat16 l0 = __float2bfloat16(a - __bfloat162float(h0));
    __nv_bfloat16 l1 = __float2bfloat16(b - __bfloat162float(h1));
    __nv_bfloat162 hv = __halves2bfloat162(h0, h1);
    __nv_bfloat162 lv = __halves2bfloat162(l0, l1);
    *(uint32_t*)(hi + idx) = *(uint32_t*)&hv;
    *(uint32_t*)(lo + idx) = *(uint32_t*)&lv;
}

// ---------------------------------------------------------------------------
// Fused CSR gather: one node per block, blockDim = F/4.
// ---------------------------------------------------------------------------
__global__ void gather_kernel(const float* __restrict__ h, const float* __restrict__ bias,
                              float* __restrict__ outf,
                              __nv_bfloat16* __restrict__ hi, __nv_bfloat16* __restrict__ lo,
                              int F, int do_relu)
{
    const int node = blockIdx.x;
    const int f0 = threadIdx.x * 4;
    const int rs = g_rowptr[node], re = g_rowptr[node + 1];
    const float di = g_dinv[node];
    const float d2 = di * di;

    float4 acc = *(const float4*)(h + (size_t)node * F + f0);
    acc.x *= d2; acc.y *= d2; acc.z *= d2; acc.w *= d2;
    if (bias) {
        float4 bb = *(const float4*)(bias + f0);
        acc.x += bb.x; acc.y += bb.y; acc.z += bb.z; acc.w += bb.w;
    }
    for (int e = rs; e < re; e++) {
        const int s = g_csrc[e];
        const float w = g_cw[e];
        float4 v = *(const float4*)(h + (size_t)s * F + f0);
        acc.x += v.x * w; acc.y += v.y * w; acc.z += v.z * w; acc.w += v.w * w;
    }
    if (do_relu) {
        acc.x = fmaxf(acc.x, 0.f); acc.y = fmaxf(acc.y, 0.f);
        acc.z = fmaxf(acc.z, 0.f); acc.w = fmaxf(acc.w, 0.f);
    }
    const size_t idx = (size_t)node * F + f0;
    if (outf) *(float4*)(outf + idx) = acc;
    if (hi) store_split4(hi, lo, idx, acc);
}

// scalar gather for F=5 (final layer): one thread per node
__global__ void gather_small_kernel(const float* __restrict__ h, const float* __restrict__ bias,
                                    float* __restrict__ outf, int F)
{
    int i = blockIdx.x * blockDim.x + threadIdx.x;
    if (i >= NNODES) return;
    const int rs = g_rowptr[i], re = g_rowptr[i + 1];
    const float di = g_dinv[i];
    const float d2 = di * di;
    float acc[8];
    for (int j = 0; j < F; j++) acc[j] = h[(size_t)i * F + j] * d2 + bias[j];
    for (int e = rs; e < re; e++) {
        const int s = g_csrc[e];
        const float w = g_cw[e];
        for (int j = 0; j < F; j++) acc[j] += h[(size_t)s * F + j] * w;
    }
    for (int j = 0; j < F; j++) outf[(size_t)i * F + j] = acc[j];
}

// ---------------------------------------------------------------------------
// W [K,N] fp32 -> Wt_hi/Wt_lo [N,K] bf16 (transpose + split)
// ---------------------------------------------------------------------------
__global__ void wconv_kernel(const float* __restrict__ W, __nv_bfloat16* __restrict__ Thi,
                             __nv_bfloat16* __restrict__ Tlo, int K, int N) {
    int idx = blockIdx.x * blockDim.x + threadIdx.x;
    if (idx >= K * N) return;
    int k = idx / N, n = idx - k * N;
    float w = W[idx];
    __nv_bfloat16 h = __float2bfloat16(w);
    Thi[(size_t)n * K + k] = h;
    Tlo[(size_t)n * K + k] = __float2bfloat16(w - __bfloat162float(h));
}

// ---------------------------------------------------------------------------
// Fused bf16x3 GEMM: C = Ahi*Whi + Alo*Whi + Ahi*Wlo, all 3 passes per chunk.
//   A*: [M,K] bf16 row-major.  W*: [N,K] bf16 row-major (= W^T, K-major).
//   Block tile 128 x BNT x 64 (BK=64), 2-stage cp.async pipeline.
//   256 thr = 8 warps (2m x 4n), warp tile 64 x BNT/4.
//   Optional epilogue: out = relu(acc + bias) -> bf16 hi/lo split buffers.
// ---------------------------------------------------------------------------
template<int BNT>
__global__ __launch_bounds__(256)
void gemm3_kernel(const __nv_bfloat16* __restrict__ Ahi, const __nv_bfloat16* __restrict__ Alo,
                  const __nv_bfloat16* __restrict__ Whi, const __nv_bfloat16* __restrict__ Wlo,
                  float* __restrict__ Cf,
                  __nv_bfloat16* __restrict__ Ehi, __nv_bfloat16* __restrict__ Elo,
                  const float* __restrict__ bias,
                  int M, int K, int N, int do_relu)
{
    constexpr int NW = BNT / 32;                    // n8 groups per warp
    constexpr int STAGE = (256 + 2 * BNT) * 128;    // bytes per stage (BK=64 -> 128B rows)
    constexpr int OFF_ALO = 128 * 128;
    constexpr int OFF_BHI = 256 * 128;
    constexpr int OFF_BLO = (256 + BNT) * 128;
    constexpr int NCH = (256 + 2 * BNT) * 8 / 256;  // 16B chunks per thread per stage

    extern __shared__ __align__(1024) char smem[];
    const uint32_t sbase = smem_u32(smem);

    const int tid = threadIdx.x, lane = tid & 31, wid = tid >> 5;
    const int wm = (wid & 1) * 64;
    const int wn = (wid >> 1) * (BNT / 4);
    const int m0 = blockIdx.y * 128;
    const int n0 = blockIdx.x * BNT;
    const int kc = K / 64;

    float acc[4][NW][4];
    #pragma unroll
    for (int mi = 0; mi < 4; mi++)
        #pragma unroll
        for (int ni = 0; ni < NW; ni++)
            #pragma unroll
            for (int q = 0; q < 4; q++) acc[mi][ni][q] = 0.f;

    auto issue = [&](int c) {
        const int st = c & 1;
        const int kk = c * 64;
        const uint32_t dstb = sbase + (uint32_t)st * STAGE;
        #pragma unroll
        for (int h = 0; h < NCH; h++) {
            const int idx = tid + h * 256;
            const int r_all = idx >> 3, ch = idx & 7;
            const __nv_bfloat16* base;
            uint32_t roff;
            int r, grow, limit;
            if (r_all < 128)            { base = Ahi; roff = 0;       r = r_all;             grow = m0 + r; limit = M; }
            else if (r_all < 256)       { base = Alo; roff = OFF_ALO; r = r_all - 128;       grow = m0 + r; limit = M; }
            else if (r_all < 256 + BNT) { base = Whi; roff = OFF_BHI; r = r_all - 256;       grow = n0 + r; limit = N; }
            else                        { base = Wlo; roff = OFF_BLO; r = r_all - 256 - BNT; grow = n0 + r; limit = N; }
            const int ok = (grow < limit) ? 16 : 0;
            const int grc = ok ? grow : 0;
            const void* g = base + (size_t)grc * K + kk + ch * 8;
            const uint32_t d = dstb + roff + (uint32_t)r * 128 + (uint32_t)((ch ^ (r & 7)) * 16);
            asm volatile("cp.async.cg.shared.global [%0], [%1], 16, %2;"
                         :: "r"(d), "l"(g), "r"(ok));
        }
        asm volatile("cp.async.commit_group;" ::: "memory");
    };

    auto compute = [&](int st) {
        const uint32_t sAh = sbase + (uint32_t)st * STAGE;
        const uint32_t sAl = sAh + OFF_ALO;
        const uint32_t sBh = sAh + OFF_BHI;
        const uint32_t sBl = sAh + OFF_BLO;
        #pragma unroll
        for (int ks = 0; ks < 4; ks++) {   // four k16 steps in BK=64
            uint32_t ah[4][4], al[4][4], b[NW][2];
            #pragma unroll
            for (int mi = 0; mi < 4; mi++) {
                const int r = wm + mi * 16 + (lane & 15);
                const int ch = ks * 2 + (lane >> 4);
                const uint32_t off = (uint32_t)r * 128 + (uint32_t)((ch ^ (r & 7)) * 16);
                asm volatile("ldmatrix.sync.aligned.m8n8.x4.shared.b16 {%0,%1,%2,%3}, [%4];"
                             : "=r"(ah[mi][0]), "=r"(ah[mi][1]), "=r"(ah[mi][2]), "=r"(ah[mi][3])
                             : "r"(sAh + off));
                asm volatile("ldmatrix.sync.aligned.m8n8.x4.shared.b16 {%0,%1,%2,%3}, [%4];"
                             : "=r"(al[mi][0]), "=r"(al[mi][1]), "=r"(al[mi][2]), "=r"(al[mi][3])
                             : "r"(sAl + off));
            }
            // Whi fragments
            #pragma unroll
            for (int g2 = 0; g2 < NW / 2; g2++) {
                const int r = wn + g2 * 16 + (lane & 7) + ((lane >> 4) << 3);
                const int ch = ks * 2 + ((lane >> 3) & 1);
                const uint32_t off = (uint32_t)r * 128 + (uint32_t)((ch ^ (r & 7)) * 16);
                asm volatile("ldmatrix.sync.aligned.m8n8.x4.shared.b16 {%0,%1,%2,%3}, [%4];"
                             : "=r"(b[g2 * 2][0]), "=r"(b[g2 * 2][1]),
                               "=r"(b[g2 * 2 + 1][0]), "=r"(b[g2 * 2 + 1][1])
                             : "r"(sBh + off));
            }
            #pragma unroll
            for (int mi = 0; mi < 4; mi++)
                #pragma unroll
                for (int ni = 0; ni < NW; ni++) {
                    asm volatile(
                        "mma.sync.aligned.m16n8k16.row.col.f32.bf16.bf16.f32 "
                        "{%0,%1,%2,%3}, {%4,%5,%6,%7}, {%8,%9}, {%0,%1,%2,%3};"
                        : "+f"(acc[mi][ni][0]), "+f"(acc[mi][ni][1]),
                          "+f"(acc[mi][ni][2]), "+f"(acc[mi][ni][3])
                        : "r"(ah[mi][0]), "r"(ah[mi][1]), "r"(ah[mi][2]), "r"(ah[mi][3]),
                          "r"(b[ni][0]), "r"(b[ni][1]));
                }
            #pragma unroll
            for (int mi = 0; mi < 4; mi++)
                #pragma unroll
                for (int ni = 0; ni < NW; ni++) {
                    asm volatile(
                        "mma.sync.aligned.m16n8k16.row.col.f32.bf16.bf16.f32 "
                        "{%0,%1,%2,%3}, {%4,%5,%6,%7}, {%8,%9}, {%0,%1,%2,%3};"
                        : "+f"(acc[mi][ni][0]), "+f"(acc[mi][ni][1]),
                          "+f"(acc[mi][ni][2]), "+f"(acc[mi][ni][3])
                        : "r"(al[mi][0]), "r"(al[mi][1]), "r"(al[mi][2]), "r"(al[mi][3]),
                          "r"(b[ni][0]), "r"(b[ni][1]));
                }
            // Wlo fragments (reuse b regs)
            #pragma unroll
            for (int g2 = 0; g2 < NW / 2; g2++) {
                const int r = wn + g2 * 16 + (lane & 7) + ((lane >> 4) << 3);
                const int ch = ks * 2 + ((lane >> 3) & 1);
                const uint32_t off = (uint32_t)r * 128 + (uint32_t)((ch ^ (r & 7)) * 16);
                asm volatile("ldmatrix.sync.aligned.m8n8.x4.shared.b16 {%0,%1,%2,%3}, [%4];"
                             : "=r"(b[g2 * 2][0]), "=r"(b[g2 * 2][1]),
                               "=r"(b[g2 * 2 + 1][0]), "=r"(b[g2 * 2 + 1][1])
                             : "r"(sBl + off));
            }
            #pragma unroll
            for (int mi = 0; mi < 4; mi++)
                #pragma unroll
                for (int ni = 0; ni < NW; ni++) {
                    asm volatile(
                        "mma.sync.aligned.m16n8k16.row.col.f32.bf16.bf16.f32 "
                        "{%0,%1,%2,%3}, {%4,%5,%6,%7}, {%8,%9}, {%0,%1,%2,%3};"
                        : "+f"(acc[mi][ni][0]), "+f"(acc[mi][ni][1]),
                          "+f"(acc[mi][ni][2]), "+f"(acc[mi][ni][3])
                        : "r"(ah[mi][0]), "r"(ah[mi][1]), "r"(ah[mi][2]), "r"(ah[mi][3]),
                          "r"(b[ni][0]), "r"(b[ni][1]));
                }
        }
    };

    issue(0);
    if (kc > 1) issue(1);
    for (int c = 0; c < kc; c++) {
        if (c + 1 < kc) {
            asm volatile("cp.async.wait_group 1;" ::: "memory");
        } else {
            asm volatile("cp.async.wait_group 0;" ::: "memory");
        }
        __syncthreads();
        compute(c & 1);
        __syncthreads();
        if (c + 2 < kc) issue(c + 2);
    }

    // epilogue
    #pragma unroll
    for (int mi = 0; mi < 4; mi++) {
        const int r0 = m0 + wm + mi * 16 + (lane >> 2);
        #pragma unroll
        for (int ni = 0; ni < NW; ni++) {
            const int col = n0 + wn + ni * 8 + 2 * (lane & 3);
            if (col >= N) continue;
            float bx = 0.f, by = 0.f;
            if (bias) { float2 bb = *(const float2*)(bias + col); bx = bb.x; by = bb.y; }
            #pragma unroll
            for (int half = 0; half < 2; half++) {
                const int r = r0 + half * 8;
                if (r >= M) continue;
                float vx = acc[mi][ni][half * 2 + 0] + bx;
                float vy = acc[mi][ni][half * 2 + 1] + by;
                if (do_relu) { vx = fmaxf(vx, 0.f); vy = fmaxf(vy, 0.f); }
                const size_t idx = (size_t)r * N + col;
                if (Cf) *(float2*)(Cf + idx) = make_float2(vx, vy);
                if (Ehi) store_split2(Ehi, Elo, idx, vx, vy);
            }
        }
    }
}

// ---------------------------------------------------------------------------
// fp32 SGEMM (tiny final layer, N=5)
// ---------------------------------------------------------------------------
#define BM 128
#define BN 128
#define BK 8
#define TM 8
#define TN 8

__global__ __launch_bounds__(256) void sgemm_kernel(
    const float* __restrict__ A, const float* __restrict__ B,
    float* __restrict__ C, int M, int K, int N)
{
    __shared__ __align__(16) float As[BK][BM];
    __shared__ __align__(16) float Bs[BK][BN];

    const int tid = threadIdx.x;
    const int block_row = blockIdx.y * BM;
    const int block_col = blockIdx.x * BN;
    const int tx = tid & 15, ty = tid >> 4;
    const int row0 = ty * TM, col0 = tx * TN;
    const int a_row = tid >> 1, a_k = (tid & 1) * 4;
    const int b_k = tid >> 5, b_col = (tid & 31) * 4;

    float acc[TM][TN];
    #pragma unroll
    for (int i = 0; i < TM; i++)
        #pragma unroll
        for (int j = 0; j < TN; j++) acc[i][j] = 0.f;

    for (int k0 = 0; k0 < K; k0 += BK) {
        float4 av = make_float4(0.f, 0.f, 0.f, 0.f);
        {
            int gr = block_row + a_row;
            if (gr < M) av = *(const float4*)(A + (size_t)gr * K + (k0 + a_k));
        }
        As[a_k + 0][a_row] = av.x;
        As[a_k + 1][a_row] = av.y;
        As[a_k + 2][a_row] = av.z;
        As[a_k + 3][a_row] = av.w;

        float4 bv = make_float4(0.f, 0.f, 0.f, 0.f);
        {
            int gc = block_col + b_col;
            const float* bp = B + (size_t)(k0 + b_k) * N;
            if ((N & 3) == 0) {
                if (gc + 3 < N) bv = *(const float4*)(bp + gc);
            } else {
                if (gc + 0 < N) bv.x = bp[gc + 0];
                if (gc + 1 < N) bv.y = bp[gc + 1];
                if (gc + 2 < N) bv.z = bp[gc + 2];
                if (gc + 3 < N) bv.w = bp[gc + 3];
            }
        }
        *(float4*)&Bs[b_k][b_col] = bv;

        __syncthreads();
        #pragma unroll
        for (int kk = 0; kk < BK; kk++) {
            float areg[TM], breg[TN];
            #pragma unroll
            for (int i = 0; i < TM; i++) areg[i] = As[kk][row0 + i];
            #pragma unroll
            for (int j = 0; j < TN; j++) breg[j] = Bs[kk][col0 + j];
            #pragma unroll
            for (int i = 0; i < TM; i++)
                #pragma unroll
                for (int j = 0; j < TN; j++)
                    acc[i][j] += areg[i] * breg[j];
        }
        __syncthreads();
    }

    #pragma unroll
    for (int i = 0; i < TM; i++) {
        int r = block_row + row0 + i;
        if (r >= M) continue;
        float* crow = C + (size_t)r * N;
        #pragma unroll
        for (int j = 0; j < TN; j++) {
            int c = block_col + col0 + j;
            if (c < N) crow[c] = acc[i][j];
        }
    }
}

// ---------------------------------------------------------------------------
// kernel_launch
// ---------------------------------------------------------------------------
extern "C" void kernel_launch(void* const* d_in, const int* in_sizes, int n_in,
                              void* d_out, int out_size)
{
    const float* x   = (const float*)d_in[0];
    const int*   ei  = (const int*)d_in[1];
    const int    E   = in_sizes[1] / 2;
    const int*   src = ei;
    const int*   dst = ei + E;

    const float* W[5];
    const float* b[5];
    for (int i = 0; i < 5; i++) {
        W[i] = (const float*)d_in[2 + 2 * i];
        b[i] = (const float*)d_in[3 + 2 * i];
    }

    float *B0, *B1, *dinv, *cw;
    int *cnt, *rowptr, *nxt, *csrc;
    __nv_bfloat16 *Ahi, *Alo, *Bhi, *Blo, *Whi, *Wlo;
    cudaGetSymbolAddress((void**)&B0,     g_B0);
    cudaGetSymbolAddress((void**)&B1,     g_B1);
    cudaGetSymbolAddress((void**)&dinv,   g_dinv);
    cudaGetSymbolAddress((void**)&cnt,    g_cnt);
    cudaGetSymbolAddress((void**)&rowptr, g_rowptr);
    cudaGetSymbolAddress((void**)&nxt,    g_next);
    cudaGetSymbolAddress((void**)&csrc,   g_csrc);
    cudaGetSymbolAddress((void**)&cw,     g_cw);
    cudaGetSymbolAddress((void**)&Ahi,    g_Ahi);
    cudaGetSymbolAddress((void**)&Alo,    g_Alo);
    cudaGetSymbolAddress((void**)&Bhi,    g_Bhi);
    cudaGetSymbolAddress((void**)&Blo,    g_Blo);
    cudaGetSymbolAddress((void**)&Whi,    g_Whi);
    cudaGetSymbolAddress((void**)&Wlo,    g_Wlo);

    const int MT = (NNODES + 127) / 128;
    constexpr int SMEM256 = (256 + 512) * 128 * 2;   // 196608
    constexpr int SMEM128 = (256 + 256) * 128 * 2;   // 131072
    static bool attr_set = false;
    if (!attr_set) {
        cudaFuncSetAttribute(gemm3_kernel<256>, cudaFuncAttributeMaxDynamicSharedMemorySize, SMEM256);
        cudaFuncSetAttribute(gemm3_kernel<128>, cudaFuncAttributeMaxDynamicSharedMemorySize, SMEM128);
        attr_set = true;
    }

    // ---- CSR build + dinv ----
    zeroi_kernel<<<(NNODES + 255) / 256, 256>>>(cnt, NNODES);
    hist_kernel<<<(E + 255) / 256, 256>>>(dst, cnt, E);
    scan_kernel<<<1, 1024>>>(cnt, rowptr, nxt, dinv);
    fill_kernel<<<(E + 255) / 256, 256>>>(src, dst, dinv, nxt, csrc, cw, E);

    float* out_h = (float*)d_out;                          // [N,192]
    float* out_o = (float*)d_out + (size_t)NNODES * 192;   // [N,5]

    auto run_wconv = [&](const float* Wp, int K, int N) {
        wconv_kernel<<<(K * N + 255) / 256, 256>>>(Wp, Whi, Wlo, K, N);
    };
    auto run_gemm = [&](const __nv_bfloat16* aHi, const __nv_bfloat16* aLo,
                        float* Cf, __nv_bfloat16* eHi, __nv_bfloat16* eLo,
                        const float* bias, int relu, int K, int N) {
        if (N % 256 == 0) {
            dim3 grid(N / 256, MT);
            gemm3_kernel<256><<<grid, 256, SMEM256>>>(aHi, aLo, Whi, Wlo, Cf, eHi, eLo,
                                                      bias, NNODES, K, N, relu);
        } else {
            dim3 grid((N + 127) / 128, MT);
            gemm3_kernel<128><<<grid, 256, SMEM128>>>(aHi, aLo, Whi, Wlo, Cf, eHi, eLo,
                                                      bias, NNODES, K, N, relu);
        }
    };

    // ---- Layer 1: aggregate FIRST on width 768 (A(xW) == (Ax)W) -> split ----
    gather_kernel<<<NNODES, 768 / 4>>>(x, nullptr, nullptr, Ahi, Alo, 768, 0);
    run_wconv(W[0], 768, 1536);
    // GEMM with fused epilogue: split(relu((Ahat x)W1 + b1)) -> (Bhi, Blo) = h1
    run_gemm(Ahi, Alo, nullptr, Bhi, Blo, b[0], 1, 768, 1536);

    // ---- Layer 2: GEMM (1536 -> 768) then fused gather+bias+relu+split ----
    run_wconv(W[1], 1536, 768);
    run_gemm(Bhi, Blo, B1, nullptr, nullptr, nullptr, 0, 1536, 768);   // B1 = h1 W2
    gather_kernel<<<NNODES, 768 / 4>>>(B1, b[1], nullptr, Ahi, Alo, 768, 1);

    // ---- Layer 3 ----
    run_wconv(W[2], 768, 384);
    run_gemm(Ahi, Alo, B1, nullptr, nullptr, nullptr, 0, 768, 384);
    gather_kernel<<<NNODES, 384 / 4>>>(B1, b[2], nullptr, Bhi, Blo, 384, 1);

    // ---- Layer 4 (fp32 h4 straight into out_h; feeds fp32 layer-5 GEMM) ----
    run_wconv(W[3], 384, 192);
    run_gemm(Bhi, Blo, B1, nullptr, nullptr, nullptr, 0, 384, 192);
    gather_kernel<<<NNODES, 192 / 4>>>(B1, b[3], out_h, nullptr, nullptr, 192, 1);

    // ---- Layer 5 (fp32, tiny) ----
    {
        dim3 grid(1, MT);
        sgemm_kernel<<<grid, 256>>>(out_h, W[4], B0, NNODES, 192, 5);
    }
    gather_small_kernel<<<(NNODES + 255) / 256, 256>>>(B0, b[4], out_o, 5);
}

// round 12
// speedup vs baseline: 3.4610x; 1.0561x over previous
#include <cuda_runtime.h>
#include <cuda_bf16.h>
#include <cstdint>

// ---------------------------------------------------------------------------
// Problem constants (fixed by the dataset)
// ---------------------------------------------------------------------------
#define NNODES 50000
#define MAXF   1536
#define MAXE   400000
#define NSB    ((NNODES + 1023) / 1024)

// Scratch (allocation-free: __device__ globals)
__device__ float g_B0[(size_t)NNODES * MAXF];
__device__ float g_B1[(size_t)NNODES * MAXF];
__device__ __nv_bfloat16 g_Ahi[(size_t)NNODES * MAXF];
__device__ __nv_bfloat16 g_Alo[(size_t)NNODES * MAXF];
__device__ __nv_bfloat16 g_Bhi[(size_t)NNODES * MAXF];
__device__ __nv_bfloat16 g_Blo[(size_t)NNODES * MAXF];
__device__ __nv_bfloat16 g_Whi[(size_t)MAXF * MAXF];
__device__ __nv_bfloat16 g_Wlo[(size_t)MAXF * MAXF];
__device__ float g_dinv[NNODES];
__device__ int   g_cnt[NNODES];
__device__ int   g_rowptr[NNODES + 1];
__device__ int   g_next[NNODES];
__device__ int   g_csrc[MAXE];
__device__ float g_cw[MAXE];
__device__ int   g_btot[64];

__device__ __forceinline__ uint32_t smem_u32(const void* p) {
    uint32_t a;
    asm("{ .reg .u64 t; cvta.to.shared.u64 t, %1; cvt.u32.u64 %0, t; }" : "=r"(a) : "l"(p));
    return a;
}

// ---------------------------------------------------------------------------
// CSR build
// ---------------------------------------------------------------------------
__global__ void zeroi_kernel(int* __restrict__ p, int n) {
    int i = blockIdx.x * blockDim.x + threadIdx.x;
    if (i < n) p[i] = 0;
}

__global__ void hist_kernel(const int* __restrict__ dst, int* __restrict__ cnt, int E) {
    int e = blockIdx.x * blockDim.x + threadIdx.x;
    if (e < E) atomicAdd(&cnt[dst[e]], 1);
}

// Blocked scan, pass 1: per-block exclusive scan, block totals, dinv.
__global__ __launch_bounds__(1024) void scan1_kernel(const int* __restrict__ cnt,
                                                     int* __restrict__ excl,
                                                     float* __restrict__ dinv) {
    __shared__ int wsum[32];
    const int tid = threadIdx.x, lane = tid & 31, wid = tid >> 5;
    const int i = blockIdx.x * 1024 + tid;
    int v = (i < NNODES) ? cnt[i] : 0;
    if (i < NNODES) dinv[i] = rsqrtf((float)v + 1.0f);
    int x = v;
    #pragma unroll
    for (int off = 1; off < 32; off <<= 1) {
        int t = __shfl_up_sync(0xFFFFFFFFu, x, off);
        if (lane >= off) x += t;
    }
    if (lane == 31) wsum[wid] = x;
    __syncthreads();
    if (wid == 0) {
        int y = wsum[lane];
        #pragma unroll
        for (int off = 1; off < 32; off <<= 1) {
            int t = __shfl_up_sync(0xFFFFFFFFu, y, off);
            if (lane >= off) y += t;
        }
        wsum[lane] = y;
    }
    __syncthreads();
    const int woff = (wid > 0) ? wsum[wid - 1] : 0;
    if (i < NNODES) excl[i] = x + woff - v;
    if (tid == 1023) g_btot[blockIdx.x] = x + woff;
}

// pass 2: scan the NSB block totals (tiny), write rowptr[NNODES]
__global__ void scan2_kernel(int* __restrict__ rowptr) {
    int run = 0;
    for (int b = 0; b < NSB; b++) { int t = g_btot[b]; g_btot[b] = run; run += t; }
    rowptr[NNODES] = run;
}

// pass 3: add block offsets, produce rowptr + next
__global__ __launch_bounds__(1024) void scan3_kernel(int* __restrict__ rowptr,
                                                     int* __restrict__ nxt) {
    const int i = blockIdx.x * 1024 + threadIdx.x;
    if (i < NNODES) {
        int v = rowptr[i] + g_btot[blockIdx.x];
        rowptr[i] = v;
        nxt[i] = v;
    }
}

__global__ void fill_kernel(const int* __restrict__ src, const int* __restrict__ dst,
                            const float* __restrict__ dinv, int* __restrict__ nxt,
                            int* __restrict__ csrc, float* __restrict__ cw, int E) {
    int e = blockIdx.x * blockDim.x + threadIdx.x;
    if (e >= E) return;
    int s = src[e], d = dst[e];
    int pos = atomicAdd(&nxt[d], 1);
    csrc[pos] = s;
    cw[pos] = dinv[s] * dinv[d];
}

// ---------------------------------------------------------------------------
// bf16 split helpers
// ---------------------------------------------------------------------------
__device__ __forceinline__ void store_split4_cs(__nv_bfloat16* hi, __nv_bfloat16* lo,
                                                size_t idx, float4 a) {
    __nv_bfloat16 h0 = __float2bfloat16(a.x), h1 = __float2bfloat16(a.y);
    __nv_bfloat16 h2 = __float2bfloat16(a.z), h3 = __float2bfloat16(a.w);
    __nv_bfloat16 l0 = __float2bfloat16(a.x - __bfloat162float(h0));
    __nv_bfloat16 l1 = __float2bfloat16(a.y - __bfloat162float(h1));
    __nv_bfloat16 l2 = __float2bfloat16(a.z - __bfloat162float(h2));
    __nv_bfloat16 l3 = __float2bfloat16(a.w - __bfloat162float(h3));
    __nv_bfloat162 hv0 = __halves2bfloat162(h0, h1), hv1 = __halves2bfloat162(h2, h3);
    __nv_bfloat162 lv0 = __halves2bfloat162(l0, l1), lv1 = __halves2bfloat162(l2, l3);
    asm volatile("st.global.cs.v2.b32 [%0], {%1,%2};"
                 :: "l"(hi + idx), "r"(*(uint32_t*)&hv0), "r"(*(uint32_t*)&hv1) : "memory");
    asm volatile("st.global.cs.v2.b32 [%0], {%1,%2};"
                 :: "l"(lo + idx), "r"(*(uint32_t*)&lv0), "r"(*(uint32_t*)&lv1) : "memory");
}

__device__ __forceinline__ void store_split2(__nv_bfloat16* hi, __nv_bfloat16* lo,
                                             size_t idx, float a, float b) {
    __nv_bfloat16 h0 = __float2bfloat16(a), h1 = __float2bfloat16(b);
    __nv_bfloat16 l0 = __float2bfloat16(a - __bfloat162float(h0));
    __nv_bfloat16 l1 = __float2bfloat16(b - __bfloat162float(h1));
    __nv_bfloat162 hv = __halves2bfloat162(h0, h1);
    __nv_bfloat162 lv = __halves2bfloat162(l0, l1);
    *(uint32_t*)(hi + idx) = *(uint32_t*)&hv;
    *(uint32_t*)(lo + idx) = *(uint32_t*)&lv;
}

// ---------------------------------------------------------------------------
// Fused CSR gather over a column chunk: one node per block,
// blockDim = chunkwidth/4, columns [fbase, fbase + 4*blockDim).
// Sequential per-chunk launches keep the input chunk L2-resident;
// outputs use streaming stores so they don't evict it.
// ---------------------------------------------------------------------------
__global__ void gather_kernel(const float* __restrict__ h, const float* __restrict__ bias,
                              float* __restrict__ outf,
                              __nv_bfloat16* __restrict__ hi, __nv_bfloat16* __restrict__ lo,
                              int F, int fbase, int do_relu)
{
    const int node = blockIdx.x;
    const int f0 = fbase + threadIdx.x * 4;
    const int rs = g_rowptr[node], re = g_rowptr[node + 1];
    const float di = g_dinv[node];
    const float d2 = di * di;

    float4 acc = *(const float4*)(h + (size_t)node * F + f0);
    acc.x *= d2; acc.y *= d2; acc.z *= d2; acc.w *= d2;
    if (bias) {
        float4 bb = *(const float4*)(bias + f0);
        acc.x += bb.x; acc.y += bb.y; acc.z += bb.z; acc.w += bb.w;
    }
    for (int e = rs; e < re; e++) {
        const int s = g_csrc[e];
        const float w = g_cw[e];
        float4 v = *(const float4*)(h + (size_t)s * F + f0);
        acc.x += v.x * w; acc.y += v.y * w; acc.z += v.z * w; acc.w += v.w * w;
    }
    if (do_relu) {
        acc.x = fmaxf(acc.x, 0.f); acc.y = fmaxf(acc.y, 0.f);
        acc.z = fmaxf(acc.z, 0.f); acc.w = fmaxf(acc.w, 0.f);
    }
    const size_t idx = (size_t)node * F + f0;
    if (outf) {
        asm volatile("st.global.cs.v4.f32 [%0], {%1,%2,%3,%4};"
                     :: "l"(outf + idx), "f"(acc.x), "f"(acc.y), "f"(acc.z), "f"(acc.w)
                     : "memory");
    }
    if (hi) store_split4_cs(hi, lo, idx, acc);
}

// ---------------------------------------------------------------------------
// W [K,N] fp32 -> Wt_hi/Wt_lo [N,K] bf16 (transpose + split)
// ---------------------------------------------------------------------------
__global__ void wconv_kernel(const float* __restrict__ W, __nv_bfloat16* __restrict__ Thi,
                             __nv_bfloat16* __restrict__ Tlo, int K, int N) {
    int idx = blockIdx.x * blockDim.x + threadIdx.x;
    if (idx >= K * N) return;
    int k = idx / N, n = idx - k * N;
    float w = W[idx];
    __nv_bfloat16 h = __float2bfloat16(w);
    Thi[(size_t)n * K + k] = h;
    Tlo[(size_t)n * K + k] = __float2bfloat16(w - __bfloat162float(h));
}

// ---------------------------------------------------------------------------
// Final layer: out[node, 0..4] = g[node, :] @ W5[192,5] + b5  (thread per node)
// ---------------------------------------------------------------------------
__global__ __launch_bounds__(256) void out5_kernel(const float* __restrict__ g,
                                                   const float* __restrict__ W5,
                                                   const float* __restrict__ b5,
                                                   float* __restrict__ out)
{
    __shared__ float sW[192 * 5];
    for (int i = threadIdx.x; i < 192 * 5; i += 256) sW[i] = W5[i];
    __syncthreads();
    const int node = blockIdx.x * 256 + threadIdx.x;
    if (node >= NNODES) return;
    float a0 = b5[0], a1 = b5[1], a2 = b5[2], a3 = b5[3], a4 = b5[4];
    const float4* gp = (const float4*)(g + (size_t)node * 192);
    #pragma unroll 4
    for (int k4 = 0; k4 < 48; k4++) {
        float4 v = gp[k4];
        const float* w = &sW[(k4 * 4) * 5];
        a0 += v.x * w[0] + v.y * w[5] + v.z * w[10] + v.w * w[15];
        a1 += v.x * w[1] + v.y * w[6] + v.z * w[11] + v.w * w[16];
        a2 += v.x * w[2] + v.y * w[7] + v.z * w[12] + v.w * w[17];
        a3 += v.x * w[3] + v.y * w[8] + v.z * w[13] + v.w * w[18];
        a4 += v.x * w[4] + v.y * w[9] + v.z * w[14] + v.w * w[19];
    }
    float* op = out + (size_t)node * 5;
    op[0] = a0; op[1] = a1; op[2] = a2; op[3] = a3; op[4] = a4;
}

// ---------------------------------------------------------------------------
// Fused bf16x3 GEMM: C = Ahi*Whi + Alo*Whi + Ahi*Wlo, all 3 passes per chunk.
//   Block tile 128 x BNT x 64 (BK=64), 2-stage cp.async pipeline.
//   Optional epilogue: out = relu(acc + bias) -> bf16 hi/lo split buffers.
// ---------------------------------------------------------------------------
template<int BNT>
__global__ __launch_bounds__(256)
void gemm3_kernel(const __nv_bfloat16* __restrict__ Ahi, const __nv_bfloat16* __restrict__ Alo,
                  const __nv_bfloat16* __restrict__ Whi, const __nv_bfloat16* __restrict__ Wlo,
                  float* __restrict__ Cf,
                  __nv_bfloat16* __restrict__ Ehi, __nv_bfloat16* __restrict__ Elo,
                  const float* __restrict__ bias,
                  int M, int K, int N, int do_relu)
{
    constexpr int NW = BNT / 32;
    constexpr int STAGE = (256 + 2 * BNT) * 128;
    constexpr int OFF_ALO = 128 * 128;
    constexpr int OFF_BHI = 256 * 128;
    constexpr int OFF_BLO = (256 + BNT) * 128;
    constexpr int NCH = (256 + 2 * BNT) * 8 / 256;

    extern __shared__ __align__(1024) char smem[];
    const uint32_t sbase = smem_u32(smem);

    const int tid = threadIdx.x, lane = tid & 31, wid = tid >> 5;
    const int wm = (wid & 1) * 64;
    const int wn = (wid >> 1) * (BNT / 4);
    const int m0 = blockIdx.y * 128;
    const int n0 = blockIdx.x * BNT;
    const int kc = K / 64;

    float acc[4][NW][4];
    #pragma unroll
    for (int mi = 0; mi < 4; mi++)
        #pragma unroll
        for (int ni = 0; ni < NW; ni++)
            #pragma unroll
            for (int q = 0; q < 4; q++) acc[mi][ni][q] = 0.f;

    auto issue = [&](int c) {
        const int st = c & 1;
        const int kk = c * 64;
        const uint32_t dstb = sbase + (uint32_t)st * STAGE;
        #pragma unroll
        for (int h = 0; h < NCH; h++) {
            const int idx = tid + h * 256;
            const int r_all = idx >> 3, ch = idx & 7;
            const __nv_bfloat16* base;
            uint32_t roff;
            int r, grow, limit;
            if (r_all < 128)            { base = Ahi; roff = 0;       r = r_all;             grow = m0 + r; limit = M; }
            else if (r_all < 256)       { base = Alo; roff = OFF_ALO; r = r_all - 128;       grow = m0 + r; limit = M; }
            else if (r_all < 256 + BNT) { base = Whi; roff = OFF_BHI; r = r_all - 256;       grow = n0 + r; limit = N; }
            else                        { base = Wlo; roff = OFF_BLO; r = r_all - 256 - BNT; grow = n0 + r; limit = N; }
            const int ok = (grow < limit) ? 16 : 0;
            const int grc = ok ? grow : 0;
            const void* g = base + (size_t)grc * K + kk + ch * 8;
            const uint32_t d = dstb + roff + (uint32_t)r * 128 + (uint32_t)((ch ^ (r & 7)) * 16);
            asm volatile("cp.async.cg.shared.global [%0], [%1], 16, %2;"
                         :: "r"(d), "l"(g), "r"(ok));
        }
        asm volatile("cp.async.commit_group;" ::: "memory");
    };

    auto compute = [&](int st) {
        const uint32_t sAh = sbase + (uint32_t)st * STAGE;
        const uint32_t sAl = sAh + OFF_ALO;
        const uint32_t sBh = sAh + OFF_BHI;
        const uint32_t sBl = sAh + OFF_BLO;
        #pragma unroll
        for (int ks = 0; ks < 4; ks++) {
            uint32_t ah[4][4], al[4][4], b[NW][2];
            #pragma unroll
            for (int mi = 0; mi < 4; mi++) {
                const int r = wm + mi * 16 + (lane & 15);
                const int ch = ks * 2 + (lane >> 4);
                const uint32_t off = (uint32_t)r * 128 + (uint32_t)((ch ^ (r & 7)) * 16);
                asm volatile("ldmatrix.sync.aligned.m8n8.x4.shared.b16 {%0,%1,%2,%3}, [%4];"
                             : "=r"(ah[mi][0]), "=r"(ah[mi][1]), "=r"(ah[mi][2]), "=r"(ah[mi][3])
                             : "r"(sAh + off));
                asm volatile("ldmatrix.sync.aligned.m8n8.x4.shared.b16 {%0,%1,%2,%3}, [%4];"
                             : "=r"(al[mi][0]), "=r"(al[mi][1]), "=r"(al[mi][2]), "=r"(al[mi][3])
                             : "r"(sAl + off));
            }
            #pragma unroll
            for (int g2 = 0; g2 < NW / 2; g2++) {
                const int r = wn + g2 * 16 + (lane & 7) + ((lane >> 4) << 3);
                const int ch = ks * 2 + ((lane >> 3) & 1);
                const uint32_t off = (uint32_t)r * 128 + (uint32_t)((ch ^ (r & 7)) * 16);
                asm volatile("ldmatrix.sync.aligned.m8n8.x4.shared.b16 {%0,%1,%2,%3}, [%4];"
                             : "=r"(b[g2 * 2][0]), "=r"(b[g2 * 2][1]),
                               "=r"(b[g2 * 2 + 1][0]), "=r"(b[g2 * 2 + 1][1])
                             : "r"(sBh + off));
            }
            #pragma unroll
            for (int mi = 0; mi < 4; mi++)
                #pragma unroll
                for (int ni = 0; ni < NW; ni++) {
                    asm volatile(
                        "mma.sync.aligned.m16n8k16.row.col.f32.bf16.bf16.f32 "
                        "{%0,%1,%2,%3}, {%4,%5,%6,%7}, {%8,%9}, {%0,%1,%2,%3};"
                        : "+f"(acc[mi][ni][0]), "+f"(acc[mi][ni][1]),
                          "+f"(acc[mi][ni][2]), "+f"(acc[mi][ni][3])
                        : "r"(ah[mi][0]), "r"(ah[mi][1]), "r"(ah[mi][2]), "r"(ah[mi][3]),
                          "r"(b[ni][0]), "r"(b[ni][1]));
                }
            #pragma unroll
            for (int mi = 0; mi < 4; mi++)
                #pragma unroll
                for (int ni = 0; ni < NW; ni++) {
                    asm volatile(
                        "mma.sync.aligned.m16n8k16.row.col.f32.bf16.bf16.f32 "
                        "{%0,%1,%2,%3}, {%4,%5,%6,%7}, {%8,%9}, {%0,%1,%2,%3};"
                        : "+f"(acc[mi][ni][0]), "+f"(acc[mi][ni][1]),
                          "+f"(acc[mi][ni][2]), "+f"(acc[mi][ni][3])
                        : "r"(al[mi][0]), "r"(al[mi][1]), "r"(al[mi][2]), "r"(al[mi][3]),
                          "r"(b[ni][0]), "r"(b[ni][1]));
                }
            #pragma unroll
            for (int g2 = 0; g2 < NW / 2; g2++) {
                const int r = wn + g2 * 16 + (lane & 7) + ((lane >> 4) << 3);
                const int ch = ks * 2 + ((lane >> 3) & 1);
                const uint32_t off = (uint32_t)r * 128 + (uint32_t)((ch ^ (r & 7)) * 16);
                asm volatile("ldmatrix.sync.aligned.m8n8.x4.shared.b16 {%0,%1,%2,%3}, [%4];"
                             : "=r"(b[g2 * 2][0]), "=r"(b[g2 * 2][1]),
                               "=r"(b[g2 * 2 + 1][0]), "=r"(b[g2 * 2 + 1][1])
                             : "r"(sBl + off));
            }
            #pragma unroll
            for (int mi = 0; mi < 4; mi++)
                #pragma unroll
                for (int ni = 0; ni < NW; ni++) {
                    asm volatile(
                        "mma.sync.aligned.m16n8k16.row.col.f32.bf16.bf16.f32 "
                        "{%0,%1,%2,%3}, {%4,%5,%6,%7}, {%8,%9}, {%0,%1,%2,%3};"
                        : "+f"(acc[mi][ni][0]), "+f"(acc[mi][ni][1]),
                          "+f"(acc[mi][ni][2]), "+f"(acc[mi][ni][3])
                        : "r"(ah[mi][0]), "r"(ah[mi][1]), "r"(ah[mi][2]), "r"(ah[mi][3]),
                          "r"(b[ni][0]), "r"(b[ni][1]));
                }
        }
    };

    issue(0);
    if (kc > 1) issue(1);
    for (int c = 0; c < kc; c++) {
        if (c + 1 < kc) {
            asm volatile("cp.async.wait_group 1;" ::: "memory");
        } else {
            asm volatile("cp.async.wait_group 0;" ::: "memory");
        }
        __syncthreads();
        compute(c & 1);
        __syncthreads();
        if (c + 2 < kc) issue(c + 2);
    }

    // epilogue
    #pragma unroll
    for (int mi = 0; mi < 4; mi++) {
        const int r0 = m0 + wm + mi * 16 + (lane >> 2);
        #pragma unroll
        for (int ni = 0; ni < NW; ni++) {
            const int col = n0 + wn + ni * 8 + 2 * (lane & 3);
            if (col >= N) continue;
            float bx = 0.f, by = 0.f;
            if (bias) { float2 bb = *(const float2*)(bias + col); bx = bb.x; by = bb.y; }
            #pragma unroll
            for (int half = 0; half < 2; half++) {
                const int r = r0 + half * 8;
                if (r >= M) continue;
                float vx = acc[mi][ni][half * 2 + 0] + bx;
                float vy = acc[mi][ni][half * 2 + 1] + by;
                if (do_relu) { vx = fmaxf(vx, 0.f); vy = fmaxf(vy, 0.f); }
                const size_t idx = (size_t)r * N + col;
                if (Cf) *(float2*)(Cf + idx) = make_float2(vx, vy);
                if (Ehi) store_split2(Ehi, Elo, idx, vx, vy);
            }
        }
    }
}

// ---------------------------------------------------------------------------
// kernel_launch
// ---------------------------------------------------------------------------
extern "C" void kernel_launch(void* const* d_in, const int* in_sizes, int n_in,
                              void* d_out, int out_size)
{
    const float* x   = (const float*)d_in[0];
    const int*   ei  = (const int*)d_in[1];
    const int    E   = in_sizes[1] / 2;
    const int*   src = ei;
    const int*   dst = ei + E;

    const float* W[5];
    const float* b[5];
    for (int i = 0; i < 5; i++) {
        W[i] = (const float*)d_in[2 + 2 * i];
        b[i] = (const float*)d_in[3 + 2 * i];
    }

    float *B0, *B1, *dinv, *cw;
    int *cnt, *rowptr, *nxt, *csrc;
    __nv_bfloat16 *Ahi, *Alo, *Bhi, *Blo, *Whi, *Wlo;
    cudaGetSymbolAddress((void**)&B0,     g_B0);
    cudaGetSymbolAddress((void**)&B1,     g_B1);
    cudaGetSymbolAddress((void**)&dinv,   g_dinv);
    cudaGetSymbolAddress((void**)&cnt,    g_cnt);
    cudaGetSymbolAddress((void**)&rowptr, g_rowptr);
    cudaGetSymbolAddress((void**)&nxt,    g_next);
    cudaGetSymbolAddress((void**)&csrc,   g_csrc);
    cudaGetSymbolAddress((void**)&cw,     g_cw);
    cudaGetSymbolAddress((void**)&Ahi,    g_Ahi);
    cudaGetSymbolAddress((void**)&Alo,    g_Alo);
    cudaGetSymbolAddress((void**)&Bhi,    g_Bhi);
    cudaGetSymbolAddress((void**)&Blo,    g_Blo);
    cudaGetSymbolAddress((void**)&Whi,    g_Whi);
    cudaGetSymbolAddress((void**)&Wlo,    g_Wlo);

    const int MT = (NNODES + 127) / 128;
    constexpr int SMEM256 = (256 + 512) * 128 * 2;   // 196608
    constexpr int SMEM128 = (256 + 256) * 128 * 2;   // 131072
    static bool attr_set = false;
    if (!attr_set) {
        cudaFuncSetAttribute(gemm3_kernel<256>, cudaFuncAttributeMaxDynamicSharedMemorySize, SMEM256);
        cudaFuncSetAttribute(gemm3_kernel<128>, cudaFuncAttributeMaxDynamicSharedMemorySize, SMEM128);
        attr_set = true;
    }

    // ---- CSR build + dinv (blocked scan) ----
    zeroi_kernel<<<(NNODES + 255) / 256, 256>>>(cnt, NNODES);
    hist_kernel<<<(E + 255) / 256, 256>>>(dst, cnt, E);
    scan1_kernel<<<NSB, 1024>>>(cnt, rowptr, dinv);
    scan2_kernel<<<1, 1>>>(rowptr);
    scan3_kernel<<<NSB, 1024>>>(rowptr, nxt);
    fill_kernel<<<(E + 255) / 256, 256>>>(src, dst, dinv, nxt, csrc, cw, E);

    float* out_h = (float*)d_out;                          // [N,192]
    float* out_o = (float*)d_out + (size_t)NNODES * 192;   // [N,5]

    auto run_wconv = [&](const float* Wp, int K, int N) {
        wconv_kernel<<<(K * N + 255) / 256, 256>>>(Wp, Whi, Wlo, K, N);
    };
    auto run_gemm = [&](const __nv_bfloat16* aHi, const __nv_bfloat16* aLo,
                        float* Cf, __nv_bfloat16* eHi, __nv_bfloat16* eLo,
                        const float* bias, int relu, int K, int N) {
        if (N % 256 == 0) {
            dim3 grid(N / 256, MT);
            gemm3_kernel<256><<<grid, 256, SMEM256>>>(aHi, aLo, Whi, Wlo, Cf, eHi, eLo,
                                                      bias, NNODES, K, N, relu);
        } else {
            dim3 grid((N + 127) / 128, MT);
            gemm3_kernel<128><<<grid, 256, SMEM128>>>(aHi, aLo, Whi, Wlo, Cf, eHi, eLo,
                                                      bias, NNODES, K, N, relu);
        }
    };
    // Column-chunked gather: 768-wide inputs run as two 384-column passes so
    // each pass's input slice (75 MB) stays L2-resident.
    auto run_gather = [&](const float* h, const float* bias, float* outf,
                          __nv_bfloat16* hi, __nv_bfloat16* lo, int F, int relu) {
        if (F == 768) {
            gather_kernel<<<NNODES, 96>>>(h, bias, outf, hi, lo, F, 0,   relu);
            gather_kernel<<<NNODES, 96>>>(h, bias, outf, hi, lo, F, 384, relu);
        } else {
            gather_kernel<<<NNODES, F / 4>>>(h, bias, outf, hi, lo, F, 0, relu);
        }
    };

    // ---- Layer 1: aggregate FIRST on width 768 (A(xW) == (Ax)W) -> split ----
    run_gather(x, nullptr, nullptr, Ahi, Alo, 768, 0);
    run_wconv(W[0], 768, 1536);
    run_gemm(Ahi, Alo, nullptr, Bhi, Blo, b[0], 1, 768, 1536);   // (Bhi,Blo) = h1

    // ---- Layer 2 ----
    run_wconv(W[1], 1536, 768);
    run_gemm(Bhi, Blo, B1, nullptr, nullptr, nullptr, 0, 1536, 768);   // B1 = h1 W2
    run_gather(B1, b[1], nullptr, Ahi, Alo, 768, 1);                   // (Ahi,Alo) = h2

    // ---- Layer 3 ----
    run_wconv(W[2], 768, 384);
    run_gemm(Ahi, Alo, B1, nullptr, nullptr, nullptr, 0, 768, 384);
    run_gather(B1, b[2], nullptr, Bhi, Blo, 384, 1);                   // (Bhi,Blo) = h3

    // ---- Layer 4 (fp32 h4 straight into out_h) ----
    run_wconv(W[3], 384, 192);
    run_gemm(Bhi, Blo, B1, nullptr, nullptr, nullptr, 0, 384, 192);
    run_gather(B1, b[3], out_h, nullptr, nullptr, 192, 1);             // out_h = h4

    // ---- Layer 5: Ahat(h4 W5) + b5 == (Ahat h4) W5 + b5 ----
    run_gather(out_h, nullptr, B0, nullptr, nullptr, 192, 0);          // B0 = Ahat h4
    out5_kernel<<<(NNODES + 255) / 256, 256>>>(B0, W[4], b[4], out_o);
}